// round 1
// baseline (speedup 1.0000x reference)
#include <cuda_runtime.h>

#define VOCAB   65
#define NEMBD   32
#define TBLK    8
#define SQRT_C  5.656854249492381f   // faithful bug: scores MULTIPLIED by sqrt(32)

// ---------------- scratch (device globals; no allocations allowed) ----------
__device__ __align__(16) float g_Qtab[520 * 32];
__device__ __align__(16) float g_Ktab[520 * 32];
__device__ __align__(16) float g_Vtab[520 * 32];
__device__ float g_loss;

__global__ void k_zero() { g_loss = 0.0f; }

// Precompute Q/K/V for every (position t, token) pair: x = tok_emb[tok]+pos_emb[t]
// Qtab[(t*65+tok)*32 + (h*8+d)] = sum_c x[c] * Wq[h][c][d]
__global__ void k_tables(const float* __restrict__ tok_emb,
                         const float* __restrict__ pos_emb,
                         const float* __restrict__ Wq,
                         const float* __restrict__ Wk,
                         const float* __restrict__ Wv) {
    int i = blockIdx.x * blockDim.x + threadIdx.x;
    if (i >= 520 * 32) return;
    int row = i >> 5;          // t*65 + tok
    int c   = i & 31;          // h*8 + d
    int t   = row / 65;
    int tok = row % 65;
    int h   = c >> 3;
    int d   = c & 7;
    float aq = 0.f, ak = 0.f, av = 0.f;
#pragma unroll
    for (int cc = 0; cc < 32; cc++) {
        float xv = tok_emb[tok * 32 + cc] + pos_emb[t * 32 + cc];
        int wi = h * 256 + cc * 8 + d;
        aq = fmaf(xv, Wq[wi], aq);
        ak = fmaf(xv, Wk[wi], ak);
        av = fmaf(xv, Wv[wi], av);
    }
    g_Qtab[i] = aq;
    g_Ktab[i] = ak;
    g_Vtab[i] = av;
}

// Main fused kernel: one thread per (sequence, token). 128 threads = 16 seqs.
__global__ __launch_bounds__(128, 4)
void k_main(const int* __restrict__ idx, const int* __restrict__ tgt,
            const float* __restrict__ Wmlp, const float* __restrict__ bmlp,
            const float* __restrict__ Wlm,  const float* __restrict__ blm,
            float* __restrict__ out, int write_logits) {
    __shared__ __align__(16) float s_wmlpT[1024];   // [c2][c]
    __shared__ float               s_bmlp[32];
    __shared__ __align__(16) float s_wlmT[2080];    // [v][c]
    __shared__ float               s_blm[66];
    __shared__ __align__(16) float s_un[8320];      // K[0..4096) | V[4096..8192); later logits stage [128][65]
    __shared__ float               s_lred[4];

    const int tid = threadIdx.x;

    // Stage weights (transposed so inner dim c is contiguous -> LDS.128)
    for (int i = tid; i < 1024; i += 128) {
        int c2 = i >> 5, c = i & 31;
        s_wmlpT[i] = Wmlp[c * 32 + c2];
    }
    if (tid < 32) s_bmlp[tid] = bmlp[tid];
    for (int i = tid; i < 2080; i += 128) {
        int v = i >> 5, c = i & 31;
        s_wlmT[i] = Wlm[c * 65 + v];
    }
    if (tid < 65) s_blm[tid] = blm[tid];

    const int ls   = tid >> 3;          // local sequence 0..15
    const int t    = tid & 7;           // token position
    const int rowg = blockIdx.x * 128 + tid;   // global token row
    const int tok  = idx[rowg];
    const int tgtv = tgt[rowg];
    const int qrow = (t * 65 + tok) * 32;

    // q into registers
    float q[32];
    {
        const float4* q4 = reinterpret_cast<const float4*>(g_Qtab + qrow);
#pragma unroll
        for (int j = 0; j < 8; j++) {
            float4 a = q4[j];
            q[4 * j + 0] = a.x; q[4 * j + 1] = a.y;
            q[4 * j + 2] = a.z; q[4 * j + 3] = a.w;
        }
    }
    // k, v rows into shared
    {
        const float4* k4 = reinterpret_cast<const float4*>(g_Ktab + qrow);
        const float4* v4 = reinterpret_cast<const float4*>(g_Vtab + qrow);
        float4* skd = reinterpret_cast<float4*>(s_un + (ls * 8 + t) * 32);
        float4* svd = reinterpret_cast<float4*>(s_un + 4096 + (ls * 8 + t) * 32);
#pragma unroll
        for (int j = 0; j < 8; j++) { skd[j] = k4[j]; svd[j] = v4[j]; }
    }
    __syncthreads();

    // ----- attention scores: sc[h][s] = SQRT_C * q_h . k_h(s), causal -----
    float sc[4][8];
    const float* kbase = s_un + ls * 256;
#pragma unroll
    for (int s = 0; s < 8; s++) {
        if (s <= t) {
            const float4* kr = reinterpret_cast<const float4*>(kbase + s * 32);
            float dh[4] = {0.f, 0.f, 0.f, 0.f};
#pragma unroll
            for (int j = 0; j < 8; j++) {          // chunk j covers c = 4j..4j+3, head = j>>1
                float4 k4 = kr[j];
                int h = j >> 1;
                dh[h] = fmaf(q[4 * j + 0], k4.x, dh[h]);
                dh[h] = fmaf(q[4 * j + 1], k4.y, dh[h]);
                dh[h] = fmaf(q[4 * j + 2], k4.z, dh[h]);
                dh[h] = fmaf(q[4 * j + 3], k4.w, dh[h]);
            }
#pragma unroll
            for (int h = 0; h < 4; h++) sc[h][s] = dh[h] * SQRT_C;
        } else {
#pragma unroll
            for (int h = 0; h < 4; h++) sc[h][s] = -1e30f;
        }
    }

    // ----- softmax per head (s=0 always valid so max is finite) -----
    float rinv[4];
#pragma unroll
    for (int h = 0; h < 4; h++) {
        float m = sc[h][0];
#pragma unroll
        for (int s = 1; s < 8; s++) m = fmaxf(m, sc[h][s]);
        float sum = 0.f;
#pragma unroll
        for (int s = 0; s < 8; s++) {
            float e = __expf(sc[h][s] - m);   // invalid: exp(-1e30-m) underflows to 0
            sc[h][s] = e;
            sum += e;
        }
        rinv[h] = __fdividef(1.0f, sum);
    }

    // ----- out = softmax @ V (concat heads) -----
    float outv[32];
#pragma unroll
    for (int c = 0; c < 32; c++) outv[c] = 0.f;
    const float* vbase = s_un + 4096 + ls * 256;
#pragma unroll
    for (int s = 0; s < 8; s++) {
        if (s <= t) {
            const float4* vr = reinterpret_cast<const float4*>(vbase + s * 32);
#pragma unroll
            for (int h = 0; h < 4; h++) {
                float p = sc[h][s] * rinv[h];
                float4 va = vr[2 * h], vb = vr[2 * h + 1];
                outv[8 * h + 0] = fmaf(p, va.x, outv[8 * h + 0]);
                outv[8 * h + 1] = fmaf(p, va.y, outv[8 * h + 1]);
                outv[8 * h + 2] = fmaf(p, va.z, outv[8 * h + 2]);
                outv[8 * h + 3] = fmaf(p, va.w, outv[8 * h + 3]);
                outv[8 * h + 4] = fmaf(p, vb.x, outv[8 * h + 4]);
                outv[8 * h + 5] = fmaf(p, vb.y, outv[8 * h + 5]);
                outv[8 * h + 6] = fmaf(p, vb.z, outv[8 * h + 6]);
                outv[8 * h + 7] = fmaf(p, vb.w, outv[8 * h + 7]);
            }
        }
    }
    __syncthreads();   // done reading K/V -> union becomes logits stage

    // ----- MLP: y = relu(outv @ Wmlp + b) -----
    float y[32];
#pragma unroll
    for (int c2 = 0; c2 < 32; c2++) {
        float a = s_bmlp[c2];
        const float4* w = reinterpret_cast<const float4*>(s_wmlpT + c2 * 32);
#pragma unroll
        for (int j = 0; j < 8; j++) {
            float4 w4 = w[j];
            a = fmaf(outv[4 * j + 0], w4.x, a);
            a = fmaf(outv[4 * j + 1], w4.y, a);
            a = fmaf(outv[4 * j + 2], w4.z, a);
            a = fmaf(outv[4 * j + 3], w4.w, a);
        }
        y[c2] = fmaxf(a, 0.f);
    }

    // ----- logits + staged store + online max / target capture -----
    float* stage = s_un;
    float m = -1e30f;
    float ltgt = 0.f;
    for (int v = 0; v < 65; v++) {
        float a = s_blm[v];
        const float4* w = reinterpret_cast<const float4*>(s_wlmT + v * 32);
#pragma unroll
        for (int j = 0; j < 8; j++) {
            float4 w4 = w[j];
            a = fmaf(y[4 * j + 0], w4.x, a);
            a = fmaf(y[4 * j + 1], w4.y, a);
            a = fmaf(y[4 * j + 2], w4.z, a);
            a = fmaf(y[4 * j + 3], w4.w, a);
        }
        stage[tid * 65 + v] = a;
        m = fmaxf(m, a);
        if (v == tgtv) ltgt = a;
    }
    // log-sum-exp second pass (reads own staged row; no sync needed)
    float sum = 0.f;
    for (int v = 0; v < 65; v++) sum += __expf(stage[tid * 65 + v] - m);
    float lossi = (m + __logf(sum)) - ltgt;

    // warp then block reduce, one atomic per block
#pragma unroll
    for (int off = 16; off > 0; off >>= 1)
        lossi += __shfl_down_sync(0xffffffffu, lossi, off);
    if ((tid & 31) == 0) s_lred[tid >> 5] = lossi;
    __syncthreads();    // also guarantees stage[] fully written for flush
    if (tid == 0)
        atomicAdd(&g_loss, s_lred[0] + s_lred[1] + s_lred[2] + s_lred[3]);

    // ----- coalesced flush: 128 rows * 65 logits = 8320 floats = 2080 float4 -----
    if (write_logits) {
        float4* o4 = reinterpret_cast<float4*>(out) + (size_t)blockIdx.x * 2080;
        const float4* st4 = reinterpret_cast<const float4*>(stage);
        for (int i = tid; i < 2080; i += 128) o4[i] = st4[i];
    }
}

__global__ void k_final(float* out, int loss_idx, float inv_n) {
    if (loss_idx >= 0) out[loss_idx] = g_loss * inv_n;
}

extern "C" void kernel_launch(void* const* d_in, const int* in_sizes, int n_in,
                              void* d_out, int out_size) {
    const int*   idx     = (const int*)d_in[0];
    const int*   targets = (const int*)d_in[1];
    const float* tok_emb = (const float*)d_in[2];
    const float* pos_emb = (const float*)d_in[3];
    const float* Wq      = (const float*)d_in[4];
    const float* Wk      = (const float*)d_in[5];
    const float* Wv      = (const float*)d_in[6];
    const float* Wmlp    = (const float*)d_in[7];
    const float* bmlp    = (const float*)d_in[8];
    const float* Wlm     = (const float*)d_in[9];
    const float* blm     = (const float*)d_in[10];
    float* out = (float*)d_out;

    const long nrows = in_sizes[0];           // B*T = 524288
    const long total = nrows * VOCAB;         // logits element count
    int write_logits = ((long)out_size >= total) ? 1 : 0;
    int loss_idx = -1;
    if ((long)out_size == total + 1) loss_idx = (int)total;
    else if (out_size == 1)          { loss_idx = 0; write_logits = 0; }

    k_zero<<<1, 1>>>();
    k_tables<<<(520 * 32 + 255) / 256, 256>>>(tok_emb, pos_emb, Wq, Wk, Wv);
    k_main<<<(int)(nrows / 128), 128>>>(idx, targets, Wmlp, bmlp, Wlm, blm,
                                        out, write_logits);
    k_final<<<1, 1>>>(out, loss_idx, 1.0f / (float)nrows);
}

// round 2
// speedup vs baseline: 1.0933x; 1.0933x over previous
#include <cuda_runtime.h>

typedef unsigned long long u64;

#define VOCAB   65
#define SQRT_C  5.656854249492381f   // faithful bug: scores MULTIPLIED by sqrt(32)

// ---------------- scratch (device globals; no allocations allowed) ----------
__device__ __align__(16) float g_Qtab[520 * 32];
__device__ __align__(16) float g_Ktab[520 * 32];
__device__ __align__(16) float g_Vtab[520 * 32];
__device__ float g_loss;

// ---------------- packed f32x2 helpers (sm_103a) ----------------------------
__device__ __forceinline__ u64 fma2(u64 a, u64 b, u64 c) {
    u64 d;
    asm("fma.rn.f32x2 %0, %1, %2, %3;" : "=l"(d) : "l"(a), "l"(b), "l"(c));
    return d;
}
__device__ __forceinline__ float hadd2(u64 a) {
    float lo, hi;
    asm("mov.b64 {%0,%1}, %2;" : "=f"(lo), "=f"(hi) : "l"(a));
    return lo + hi;
}
__device__ __forceinline__ u64 pack2(float lo, float hi) {
    u64 r;
    asm("mov.b64 %0, {%1,%2};" : "=l"(r) : "f"(lo), "f"(hi));
    return r;
}

// Precompute Q/K/V for every (position t, token) pair: x = tok_emb[tok]+pos_emb[t]
__global__ void k_tables(const float* __restrict__ tok_emb,
                         const float* __restrict__ pos_emb,
                         const float* __restrict__ Wq,
                         const float* __restrict__ Wk,
                         const float* __restrict__ Wv) {
    int i = blockIdx.x * blockDim.x + threadIdx.x;
    if (i == 0) g_loss = 0.0f;
    if (i >= 520 * 32) return;
    int row = i >> 5;          // t*65 + tok
    int c   = i & 31;          // h*8 + d
    int t   = row / 65;
    int tok = row % 65;
    int h   = c >> 3;
    int d   = c & 7;
    float aq = 0.f, ak = 0.f, av = 0.f;
#pragma unroll
    for (int cc = 0; cc < 32; cc++) {
        float xv = tok_emb[tok * 32 + cc] + pos_emb[t * 32 + cc];
        int wi = h * 256 + cc * 8 + d;
        aq = fmaf(xv, Wq[wi], aq);
        ak = fmaf(xv, Wk[wi], ak);
        av = fmaf(xv, Wv[wi], av);
    }
    g_Qtab[i] = aq;
    g_Ktab[i] = ak;
    g_Vtab[i] = av;
}

#define KV_LS_STRIDE 264   // 264 floats per sequence: +8 banks per ls -> conflict-free

// Main fused kernel: one thread per (sequence, token). 128 threads = 16 seqs.
__global__ __launch_bounds__(128, 4)
void k_main(const int* __restrict__ idx, const int* __restrict__ tgt,
            const float* __restrict__ Wmlp, const float* __restrict__ bmlp,
            const float* __restrict__ Wlm,  const float* __restrict__ blm,
            float* __restrict__ out, int write_logits) {
    __shared__ __align__(16) float s_wmlpT[1024];   // [c2][c]  (transposed)
    __shared__ float               s_bmlp[32];
    __shared__ __align__(16) float s_wlmT[2080];    // [v][c]   (transposed)
    __shared__ float               s_blm[66];
    // union: K at [ls*264 + s*32], V at [4224 + ls*264 + s*32]; later logits stage [128][65]
    __shared__ __align__(16) float s_un[8448];
    __shared__ float               s_lred[4];

    const int tid = threadIdx.x;

    // Stage weights (transposed so contraction dim c is contiguous -> 128-bit LDS)
    for (int i = tid; i < 1024; i += 128) {
        int c2 = i >> 5, c = i & 31;
        s_wmlpT[i] = Wmlp[c * 32 + c2];
    }
    if (tid < 32) s_bmlp[tid] = bmlp[tid];
    for (int i = tid; i < 2080; i += 128) {
        int v = i >> 5, c = i & 31;
        s_wlmT[i] = Wlm[c * 65 + v];
    }
    if (tid < 65) s_blm[tid] = blm[tid];

    const int ls   = tid >> 3;                 // local sequence 0..15
    const int t    = tid & 7;                  // token position
    const int rowg = blockIdx.x * 128 + tid;   // global token row
    const int tok  = idx[rowg];
    const int tgtv = tgt[rowg];
    const int qrow = (t * 65 + tok) * 32;

    // q into packed registers: q2[j] = (q[2j], q[2j+1])
    u64 q2[16];
    {
        const ulonglong2* q4 = reinterpret_cast<const ulonglong2*>(g_Qtab + qrow);
#pragma unroll
        for (int j = 0; j < 8; j++) {
            ulonglong2 a = q4[j];
            q2[2 * j]     = a.x;
            q2[2 * j + 1] = a.y;
        }
    }
    // k, v rows into shared (own row; padded ls stride)
    {
        const float4* k4 = reinterpret_cast<const float4*>(g_Ktab + qrow);
        const float4* v4 = reinterpret_cast<const float4*>(g_Vtab + qrow);
        float4* skd = reinterpret_cast<float4*>(s_un + ls * KV_LS_STRIDE + t * 32);
        float4* svd = reinterpret_cast<float4*>(s_un + 4224 + ls * KV_LS_STRIDE + t * 32);
#pragma unroll
        for (int j = 0; j < 8; j++) { skd[j] = k4[j]; svd[j] = v4[j]; }
    }
    __syncthreads();

    // ----- attention scores: sc[h][s] = SQRT_C * q_h . k_h(s), causal -----
    float sc[4][8];
    const float* kbase = s_un + ls * KV_LS_STRIDE;
#pragma unroll
    for (int s = 0; s < 8; s++) {
        const ulonglong2* kr = reinterpret_cast<const ulonglong2*>(kbase + s * 32);
#pragma unroll
        for (int h = 0; h < 4; h++) {
            ulonglong2 a = kr[2 * h];
            ulonglong2 b = kr[2 * h + 1];
            u64 acc = 0ull;                       // (0.0f, 0.0f)
            acc = fma2(q2[4 * h + 0], a.x, acc);
            acc = fma2(q2[4 * h + 1], a.y, acc);
            acc = fma2(q2[4 * h + 2], b.x, acc);
            acc = fma2(q2[4 * h + 3], b.y, acc);
            float dh = hadd2(acc);
            sc[h][s] = (s <= t) ? dh * SQRT_C : -1e30f;
        }
    }

    // ----- softmax per head (s=0 always valid so max is finite) -----
    float rinv[4];
#pragma unroll
    for (int h = 0; h < 4; h++) {
        float m = sc[h][0];
#pragma unroll
        for (int s = 1; s < 8; s++) m = fmaxf(m, sc[h][s]);
        float sum = 0.f;
#pragma unroll
        for (int s = 0; s < 8; s++) {
            float e = __expf(sc[h][s] - m);   // masked lanes underflow to 0
            sc[h][s] = e;
            sum += e;
        }
        rinv[h] = __fdividef(1.0f, sum);
    }

    // ----- out = softmax @ V (concat heads), packed pairs along d -----
    u64 outv2[16];
#pragma unroll
    for (int j = 0; j < 16; j++) outv2[j] = 0ull;
    const float* vbase = s_un + 4224 + ls * KV_LS_STRIDE;
#pragma unroll
    for (int s = 0; s < 8; s++) {
        const ulonglong2* vr = reinterpret_cast<const ulonglong2*>(vbase + s * 32);
#pragma unroll
        for (int h = 0; h < 4; h++) {
            float p = sc[h][s] * rinv[h];        // 0 for masked s
            u64 p2 = pack2(p, p);
            ulonglong2 a = vr[2 * h];
            ulonglong2 b = vr[2 * h + 1];
            outv2[4 * h + 0] = fma2(p2, a.x, outv2[4 * h + 0]);
            outv2[4 * h + 1] = fma2(p2, a.y, outv2[4 * h + 1]);
            outv2[4 * h + 2] = fma2(p2, b.x, outv2[4 * h + 2]);
            outv2[4 * h + 3] = fma2(p2, b.y, outv2[4 * h + 3]);
        }
    }
    __syncthreads();   // done reading K/V -> union becomes logits stage

    // ----- MLP: y = relu(outv @ Wmlp + b); contraction packed along c -----
    float y[32];
#pragma unroll
    for (int c2 = 0; c2 < 32; c2++) {
        const ulonglong2* w = reinterpret_cast<const ulonglong2*>(s_wmlpT + c2 * 32);
        u64 acc = 0ull;
#pragma unroll
        for (int j = 0; j < 8; j++) {
            ulonglong2 ww = w[j];
            acc = fma2(outv2[2 * j],     ww.x, acc);
            acc = fma2(outv2[2 * j + 1], ww.y, acc);
        }
        y[c2] = fmaxf(hadd2(acc) + s_bmlp[c2], 0.f);
    }
    u64 y2[16];
#pragma unroll
    for (int j = 0; j < 16; j++) y2[j] = pack2(y[2 * j], y[2 * j + 1]);

    // ----- logits + staged store + online max / target capture -----
    float* stage = s_un;
    float m = -1e30f;
    float ltgt = 0.f;
    for (int v = 0; v < 65; v++) {
        const ulonglong2* w = reinterpret_cast<const ulonglong2*>(s_wlmT + v * 32);
        u64 acc = 0ull;
#pragma unroll
        for (int j = 0; j < 8; j++) {
            ulonglong2 ww = w[j];
            acc = fma2(y2[2 * j],     ww.x, acc);
            acc = fma2(y2[2 * j + 1], ww.y, acc);
        }
        float a = hadd2(acc) + s_blm[v];
        stage[tid * 65 + v] = a;
        m = fmaxf(m, a);
        ltgt = (v == tgtv) ? a : ltgt;
    }
    // log-sum-exp second pass (reads own staged row; no sync needed)
    float sum = 0.f;
    for (int v = 0; v < 65; v++) sum += __expf(stage[tid * 65 + v] - m);
    float lossi = (m + __logf(sum)) - ltgt;

    // warp then block reduce, one atomic per block
#pragma unroll
    for (int off = 16; off > 0; off >>= 1)
        lossi += __shfl_down_sync(0xffffffffu, lossi, off);
    if ((tid & 31) == 0) s_lred[tid >> 5] = lossi;
    __syncthreads();    // also guarantees stage[] fully written for flush
    if (tid == 0)
        atomicAdd(&g_loss, s_lred[0] + s_lred[1] + s_lred[2] + s_lred[3]);

    // ----- coalesced flush: 128 rows * 65 logits = 8320 floats = 2080 float4 -----
    if (write_logits) {
        float4* o4 = reinterpret_cast<float4*>(out) + (size_t)blockIdx.x * 2080;
        const float4* st4 = reinterpret_cast<const float4*>(stage);
        for (int i = tid; i < 2080; i += 128) o4[i] = st4[i];
    }
}

__global__ void k_final(float* out, int loss_idx, float inv_n) {
    if (loss_idx >= 0) out[loss_idx] = g_loss * inv_n;
}

__global__ void k_nop() {}   // pads the launch pattern so ncu -s 5 lands on k_main

extern "C" void kernel_launch(void* const* d_in, const int* in_sizes, int n_in,
                              void* d_out, int out_size) {
    const int*   idx     = (const int*)d_in[0];
    const int*   targets = (const int*)d_in[1];
    const float* tok_emb = (const float*)d_in[2];
    const float* pos_emb = (const float*)d_in[3];
    const float* Wq      = (const float*)d_in[4];
    const float* Wk      = (const float*)d_in[5];
    const float* Wv      = (const float*)d_in[6];
    const float* Wmlp    = (const float*)d_in[7];
    const float* bmlp    = (const float*)d_in[8];
    const float* Wlm     = (const float*)d_in[9];
    const float* blm     = (const float*)d_in[10];
    float* out = (float*)d_out;

    const long nrows = in_sizes[0];           // B*T = 524288
    const long total = nrows * VOCAB;         // logits element count
    int write_logits = ((long)out_size >= total) ? 1 : 0;
    int loss_idx = -1;
    if ((long)out_size == total + 1) loss_idx = (int)total;
    else if (out_size == 1)          { loss_idx = 0; write_logits = 0; }

    k_tables<<<(520 * 32 + 255) / 256, 256>>>(tok_emb, pos_emb, Wq, Wk, Wv);
    k_main<<<(int)(nrows / 128), 128>>>(idx, targets, Wmlp, bmlp, Wlm, blm,
                                        out, write_logits);
    k_final<<<1, 1>>>(out, loss_idx, 1.0f / (float)nrows);
    k_nop<<<1, 1>>>();
}

// round 3
// speedup vs baseline: 1.1088x; 1.0141x over previous
#include <cuda_runtime.h>

typedef unsigned long long u64;

#define VOCAB   65
#define SQRT_C  5.656854249492381f   // faithful bug: scores MULTIPLIED by sqrt(32)

// ---------------- scratch (device globals; no allocations allowed) ----------
__device__ __align__(16) float g_Qtab[520 * 32];
__device__ __align__(16) float g_Ktab[520 * 32];
__device__ __align__(16) float g_Vtab[520 * 32];
__device__ float    g_loss;
__device__ unsigned g_done;

// ---------------- packed f32x2 helpers (sm_103a) ----------------------------
__device__ __forceinline__ u64 fma2(u64 a, u64 b, u64 c) {
    u64 d;
    asm("fma.rn.f32x2 %0, %1, %2, %3;" : "=l"(d) : "l"(a), "l"(b), "l"(c));
    return d;
}
__device__ __forceinline__ float hadd2(u64 a) {
    float lo, hi;
    asm("mov.b64 {%0,%1}, %2;" : "=f"(lo), "=f"(hi) : "l"(a));
    return lo + hi;
}
__device__ __forceinline__ u64 pack2(float lo, float hi) {
    u64 r;
    asm("mov.b64 %0, {%1,%2};" : "=l"(r) : "f"(lo), "f"(hi));
    return r;
}
__device__ __forceinline__ float lo2(u64 a) {
    float lo, hi;
    asm("mov.b64 {%0,%1}, %2;" : "=f"(lo), "=f"(hi) : "l"(a));
    return lo;
}
__device__ __forceinline__ float hi2(u64 a) {
    float lo, hi;
    asm("mov.b64 {%0,%1}, %2;" : "=f"(lo), "=f"(hi) : "l"(a));
    return hi;
}

// Precompute Q/K/V for every (position t, token): x = tok_emb[tok]+pos_emb[t]
__global__ void k_tables(const float* __restrict__ tok_emb,
                         const float* __restrict__ pos_emb,
                         const float* __restrict__ Wq,
                         const float* __restrict__ Wk,
                         const float* __restrict__ Wv) {
    int i = blockIdx.x * blockDim.x + threadIdx.x;
    if (i == 0) { g_loss = 0.0f; g_done = 0u; }
    if (i >= 520 * 32) return;
    int row = i >> 5;          // t*65 + tok
    int c   = i & 31;          // h*8 + d
    int t   = row / 65;
    int tok = row % 65;
    int h   = c >> 3;
    int d   = c & 7;
    float aq = 0.f, ak = 0.f, av = 0.f;
#pragma unroll
    for (int cc = 0; cc < 32; cc++) {
        float xv = tok_emb[tok * 32 + cc] + pos_emb[t * 32 + cc];
        int wi = h * 256 + cc * 8 + d;
        aq = fmaf(xv, Wq[wi], aq);
        ak = fmaf(xv, Wk[wi], ak);
        av = fmaf(xv, Wv[wi], av);
    }
    g_Qtab[i] = aq;
    g_Ktab[i] = ak;
    g_Vtab[i] = av;
}

#define KV_LS_STRIDE 264   // floats per sequence: +8 banks per ls -> conflict-free
#define WLM_STRIDE   68    // padded vocab row stride (16B-aligned rows)

// Main fused kernel: one thread per (sequence, token). 128 threads = 16 seqs.
__global__ __launch_bounds__(128, 4)
void k_main(const int* __restrict__ idx, const int* __restrict__ tgt,
            const float* __restrict__ Wmlp, const float* __restrict__ bmlp,
            const float* __restrict__ Wlm,  const float* __restrict__ blm,
            float* __restrict__ out, int write_logits,
            int loss_idx, float inv_n, int nblocks) {
    __shared__ __align__(16) float s_wmlp[1024];    // [c][c2]  original layout
    __shared__ __align__(16) float s_bmlp[32];
    __shared__ __align__(16) float s_wlm[32 * WLM_STRIDE]; // [c][v] padded to 68
    __shared__ __align__(16) float s_blm[68];
    // union: K at [ls*264+s*32], V at [4224+...]; later logits stage [128][66]
    __shared__ __align__(16) float s_un[8448];
    __shared__ float               s_lred[4];

    const int tid = threadIdx.x;

    // Stage weights in ORIGINAL layout (output dim contiguous)
    for (int i = tid; i < 1024; i += 128) s_wmlp[i] = Wmlp[i];
    if (tid < 32) s_bmlp[tid] = bmlp[tid];
    for (int i = tid; i < 32 * WLM_STRIDE; i += 128) {
        int c = i / WLM_STRIDE, v = i - c * WLM_STRIDE;
        s_wlm[i] = (v < 65) ? Wlm[c * 65 + v] : 0.0f;
    }
    if (tid < 68) s_blm[tid] = (tid < 65) ? blm[tid] : ((tid == 65) ? -1e30f : 0.0f);

    const int ls   = tid >> 3;                 // local sequence 0..15
    const int t    = tid & 7;                  // token position
    const int rowg = blockIdx.x * 128 + tid;   // global token row
    const int tok  = idx[rowg];
    const int tgtv = tgt[rowg];
    const int qrow = (t * 65 + tok) * 32;

    // q into packed registers: q2[j] = (q[2j], q[2j+1])
    u64 q2[16];
    {
        const ulonglong2* q4 = reinterpret_cast<const ulonglong2*>(g_Qtab + qrow);
#pragma unroll
        for (int j = 0; j < 8; j++) {
            ulonglong2 a = q4[j];
            q2[2 * j]     = a.x;
            q2[2 * j + 1] = a.y;
        }
    }
    // k, v rows into shared (own row; padded ls stride)
    {
        const float4* k4 = reinterpret_cast<const float4*>(g_Ktab + qrow);
        const float4* v4 = reinterpret_cast<const float4*>(g_Vtab + qrow);
        float4* skd = reinterpret_cast<float4*>(s_un + ls * KV_LS_STRIDE + t * 32);
        float4* svd = reinterpret_cast<float4*>(s_un + 4224 + ls * KV_LS_STRIDE + t * 32);
#pragma unroll
        for (int j = 0; j < 8; j++) { skd[j] = k4[j]; svd[j] = v4[j]; }
    }
    __syncthreads();

    // ----- attention scores: sc[h][s] = SQRT_C * q_h . k_h(s), causal -----
    float sc[4][8];
    const float* kbase = s_un + ls * KV_LS_STRIDE;
#pragma unroll
    for (int s = 0; s < 8; s++) {
        const ulonglong2* kr = reinterpret_cast<const ulonglong2*>(kbase + s * 32);
#pragma unroll
        for (int h = 0; h < 4; h++) {
            ulonglong2 a = kr[2 * h];
            ulonglong2 b = kr[2 * h + 1];
            u64 acc0 = 0ull, acc1 = 0ull;         // two chains
            acc0 = fma2(q2[4 * h + 0], a.x, acc0);
            acc1 = fma2(q2[4 * h + 1], a.y, acc1);
            acc0 = fma2(q2[4 * h + 2], b.x, acc0);
            acc1 = fma2(q2[4 * h + 3], b.y, acc1);
            float dh = hadd2(acc0) + hadd2(acc1);
            sc[h][s] = (s <= t) ? dh * SQRT_C : -1e30f;
        }
    }

    // ----- softmax per head -----
    float rinv[4];
#pragma unroll
    for (int h = 0; h < 4; h++) {
        float m = sc[h][0];
#pragma unroll
        for (int s = 1; s < 8; s++) m = fmaxf(m, sc[h][s]);
        float sum = 0.f;
#pragma unroll
        for (int s = 0; s < 8; s++) {
            float e = __expf(sc[h][s] - m);   // masked lanes underflow to 0
            sc[h][s] = e;
            sum += e;
        }
        rinv[h] = __fdividef(1.0f, sum);
    }

    // ----- out = softmax @ V (concat heads), packed pairs along d -----
    u64 outv2[16];
#pragma unroll
    for (int j = 0; j < 16; j++) outv2[j] = 0ull;
    const float* vbase = s_un + 4224 + ls * KV_LS_STRIDE;
#pragma unroll
    for (int s = 0; s < 8; s++) {
        const ulonglong2* vr = reinterpret_cast<const ulonglong2*>(vbase + s * 32);
#pragma unroll
        for (int h = 0; h < 4; h++) {
            float p = sc[h][s] * rinv[h];        // 0 for masked s
            u64 p2 = pack2(p, p);
            ulonglong2 a = vr[2 * h];
            ulonglong2 b = vr[2 * h + 1];
            outv2[4 * h + 0] = fma2(p2, a.x, outv2[4 * h + 0]);
            outv2[4 * h + 1] = fma2(p2, a.y, outv2[4 * h + 1]);
            outv2[4 * h + 2] = fma2(p2, b.x, outv2[4 * h + 2]);
            outv2[4 * h + 3] = fma2(p2, b.y, outv2[4 * h + 3]);
        }
    }
    // unpack attention output to scalars (register-pair aliasing, ~free)
    float ov[32];
#pragma unroll
    for (int j = 0; j < 16; j++) { ov[2 * j] = lo2(outv2[j]); ov[2 * j + 1] = hi2(outv2[j]); }
    __syncthreads();   // done reading K/V -> union becomes logits stage

    // ----- MLP: y = relu(ov @ Wmlp + b); packed along OUTPUT dim c2 -----
    // 16 independent accumulator pairs, bias folded into init.
    u64 macc[16];
    {
        const u64* b2 = reinterpret_cast<const u64*>(s_bmlp);
#pragma unroll
        for (int j = 0; j < 16; j++) macc[j] = b2[j];
    }
#pragma unroll
    for (int c = 0; c < 32; c++) {
        u64 xb = pack2(ov[c], ov[c]);
        const ulonglong2* wr = reinterpret_cast<const ulonglong2*>(s_wmlp + c * 32);
#pragma unroll
        for (int jj = 0; jj < 8; jj++) {
            ulonglong2 w = wr[jj];
            macc[2 * jj]     = fma2(xb, w.x, macc[2 * jj]);
            macc[2 * jj + 1] = fma2(xb, w.y, macc[2 * jj + 1]);
        }
    }
    float y[32];
#pragma unroll
    for (int j = 0; j < 16; j++) {
        y[2 * j]     = fmaxf(lo2(macc[j]), 0.f);
        y[2 * j + 1] = fmaxf(hi2(macc[j]), 0.f);
    }

    // ----- lm-head: logits packed along vocab; online LSE; write-only stage --
    float* stagerow = s_un + tid * 66;
    u64*   stage2   = reinterpret_cast<u64*>(stagerow);
    float m = -1e30f, sum = 0.f;

#pragma unroll
    for (int chunk = 0; chunk < 4; chunk++) {      // pairs [8*chunk, 8*chunk+8)
        const int vb = chunk * 16;                 // vocab base
        u64 acc[8];
        {
            const u64* b2 = reinterpret_cast<const u64*>(s_blm + vb);
#pragma unroll
            for (int p = 0; p < 8; p++) acc[p] = b2[p];
        }
#pragma unroll
        for (int c = 0; c < 32; c++) {
            u64 yb = pack2(y[c], y[c]);
            const ulonglong2* wr =
                reinterpret_cast<const ulonglong2*>(s_wlm + c * WLM_STRIDE + vb);
#pragma unroll
            for (int q = 0; q < 4; q++) {
                ulonglong2 w = wr[q];
                acc[2 * q]     = fma2(yb, w.x, acc[2 * q]);
                acc[2 * q + 1] = fma2(yb, w.y, acc[2 * q + 1]);
            }
        }
        // store + online LSE over these 16 logits
        float cm = -1e30f;
        float l[16];
#pragma unroll
        for (int p = 0; p < 8; p++) {
            stage2[chunk * 8 + p] = acc[p];
            l[2 * p] = lo2(acc[p]); l[2 * p + 1] = hi2(acc[p]);
            cm = fmaxf(cm, fmaxf(l[2 * p], l[2 * p + 1]));
        }
        float mn = fmaxf(m, cm);
        float s2 = sum * __expf(m - mn);
#pragma unroll
        for (int p = 0; p < 16; p++) s2 += __expf(l[p] - mn);
        m = mn; sum = s2;
    }
    {   // epilogue pair: v = 64 (real), v = 65 (pad, bias -1e30 -> exp 0)
        const u64* b2 = reinterpret_cast<const u64*>(s_blm + 64);
        u64 acc = b2[0];
#pragma unroll
        for (int c = 0; c < 32; c++) {
            u64 yb = pack2(y[c], y[c]);
            const u64* w1 = reinterpret_cast<const u64*>(s_wlm + c * WLM_STRIDE + 64);
            acc = fma2(yb, w1[0], acc);
        }
        float l64 = lo2(acc);
        stagerow[64] = l64;
        float mn = fmaxf(m, l64);
        sum = sum * __expf(m - mn) + __expf(l64 - mn);
        m = mn;
    }
    float ltgt  = stagerow[tgtv];              // own row, no sync needed
    float lossi = (m + __logf(sum)) - ltgt;

    // warp then block reduce, one atomic per block; last block writes mean
#pragma unroll
    for (int off = 16; off > 0; off >>= 1)
        lossi += __shfl_down_sync(0xffffffffu, lossi, off);
    if ((tid & 31) == 0) s_lred[tid >> 5] = lossi;
    __syncthreads();    // also guarantees stage[] fully written for flush
    if (tid == 0) {
        atomicAdd(&g_loss, s_lred[0] + s_lred[1] + s_lred[2] + s_lred[3]);
        __threadfence();
        unsigned prev = atomicAdd(&g_done, 1u);
        if ((int)prev == nblocks - 1 && loss_idx >= 0)
            out[loss_idx] = g_loss * inv_n;
    }

    // ----- coalesced flush: 128 rows x 65 logits (stage stride 66) -----
    if (write_logits) {
        float* ob = out + (size_t)blockIdx.x * 8320;
        for (int i = tid; i < 8320; i += 128) {
            int row = i / 65;
            int v   = i - row * 65;
            ob[i] = s_un[row * 66 + v];
        }
    }
}

extern "C" void kernel_launch(void* const* d_in, const int* in_sizes, int n_in,
                              void* d_out, int out_size) {
    const int*   idx     = (const int*)d_in[0];
    const int*   targets = (const int*)d_in[1];
    const float* tok_emb = (const float*)d_in[2];
    const float* pos_emb = (const float*)d_in[3];
    const float* Wq      = (const float*)d_in[4];
    const float* Wk      = (const float*)d_in[5];
    const float* Wv      = (const float*)d_in[6];
    const float* Wmlp    = (const float*)d_in[7];
    const float* bmlp    = (const float*)d_in[8];
    const float* Wlm     = (const float*)d_in[9];
    const float* blm     = (const float*)d_in[10];
    float* out = (float*)d_out;

    const long nrows = in_sizes[0];           // B*T = 524288
    const long total = nrows * VOCAB;         // logits element count
    int write_logits = ((long)out_size >= total) ? 1 : 0;
    int loss_idx = -1;
    if ((long)out_size == total + 1) loss_idx = (int)total;
    else if (out_size == 1)          { loss_idx = 0; write_logits = 0; }

    int nblocks = (int)(nrows / 128);
    k_tables<<<(520 * 32 + 255) / 256, 256>>>(tok_emb, pos_emb, Wq, Wk, Wv);
    k_main<<<nblocks, 128>>>(idx, targets, Wmlp, bmlp, Wlm, blm,
                             out, write_logits, loss_idx,
                             1.0f / (float)nrows, nblocks);
}

// round 4
// speedup vs baseline: 1.2122x; 1.0933x over previous
#include <cuda_runtime.h>

typedef unsigned long long u64;

#define VOCAB   65
#define SQRT_C  5.656854249492381f   // faithful bug: scores MULTIPLIED by sqrt(32)

// ---------------- scratch (device globals; no allocations allowed) ----------
__device__ __align__(16) float g_Qtab[520 * 32];
__device__ __align__(16) float g_Ktab[520 * 32];
__device__ __align__(16) float g_Vtab[520 * 32];
__device__ float    g_loss;
__device__ unsigned g_done;

// ---------------- weights in constant memory (uniform access, off-L1) -------
#define WLM_STRIDE 68   // padded so every 16-wide vocab chunk is 16B-aligned
__constant__ __align__(16) float c_wmlp[32 * 32];        // [c][c2]
__constant__ __align__(16) float c_bmlp[32];
__constant__ __align__(16) float c_wlm[32 * WLM_STRIDE]; // [c][v] padded
__constant__ __align__(16) float c_blm[68];              // pads stay 0 (unused)

// ---------------- packed f32x2 helpers (sm_103a) ----------------------------
__device__ __forceinline__ u64 fma2(u64 a, u64 b, u64 c) {
    u64 d;
    asm("fma.rn.f32x2 %0, %1, %2, %3;" : "=l"(d) : "l"(a), "l"(b), "l"(c));
    return d;
}
__device__ __forceinline__ float hadd2(u64 a) {
    float lo, hi;
    asm("mov.b64 {%0,%1}, %2;" : "=f"(lo), "=f"(hi) : "l"(a));
    return lo + hi;
}
__device__ __forceinline__ u64 pack2(float lo, float hi) {
    u64 r;
    asm("mov.b64 %0, {%1,%2};" : "=l"(r) : "f"(lo), "f"(hi));
    return r;
}
__device__ __forceinline__ float lo2(u64 a) {
    float lo, hi;
    asm("mov.b64 {%0,%1}, %2;" : "=f"(lo), "=f"(hi) : "l"(a));
    return lo;
}
__device__ __forceinline__ float hi2(u64 a) {
    float lo, hi;
    asm("mov.b64 {%0,%1}, %2;" : "=f"(lo), "=f"(hi) : "l"(a));
    return hi;
}
__device__ __forceinline__ u64 ldc2(const float* p) {   // 8B constant load
    return *reinterpret_cast<const u64*>(p);
}

// Precompute Q/K/V for every (position t, token): x = tok_emb[tok]+pos_emb[t]
__global__ void k_tables(const float* __restrict__ tok_emb,
                         const float* __restrict__ pos_emb,
                         const float* __restrict__ Wq,
                         const float* __restrict__ Wk,
                         const float* __restrict__ Wv) {
    int i = blockIdx.x * blockDim.x + threadIdx.x;
    if (i == 0) { g_loss = 0.0f; g_done = 0u; }
    if (i >= 520 * 32) return;
    int row = i >> 5;          // t*65 + tok
    int c   = i & 31;          // h*8 + d
    int t   = row / 65;
    int tok = row % 65;
    int h   = c >> 3;
    int d   = c & 7;
    float aq = 0.f, ak = 0.f, av = 0.f;
#pragma unroll
    for (int cc = 0; cc < 32; cc++) {
        float xv = tok_emb[tok * 32 + cc] + pos_emb[t * 32 + cc];
        int wi = h * 256 + cc * 8 + d;
        aq = fmaf(xv, Wq[wi], aq);
        ak = fmaf(xv, Wk[wi], ak);
        av = fmaf(xv, Wv[wi], av);
    }
    g_Qtab[i] = aq;
    g_Ktab[i] = ak;
    g_Vtab[i] = av;
}

#define KV_LS_STRIDE 264   // floats per sequence: +8 banks per ls -> conflict-free

// Main fused kernel: one thread per (sequence, token). 128 threads = 16 seqs.
__global__ __launch_bounds__(128, 4)
void k_main(const int* __restrict__ idx, const int* __restrict__ tgt,
            float* __restrict__ out, int write_logits,
            int loss_idx, float inv_n, int nblocks) {
    // union: K at [ls*264+s*32], V at [4224+...]; later logits stage [128][65] dense
    __shared__ __align__(16) float s_un[8448];
    __shared__ float               s_lred[4];

    const int tid  = threadIdx.x;
    const int ls   = tid >> 3;                 // local sequence 0..15
    const int t    = tid & 7;                  // token position
    const int rowg = blockIdx.x * 128 + tid;   // global token row
    const int tok  = idx[rowg];
    const int tgtv = tgt[rowg];
    const int qrow = (t * 65 + tok) * 32;

    // q into packed registers: q2[j] = (q[2j], q[2j+1])
    u64 q2[16];
    {
        const ulonglong2* q4 = reinterpret_cast<const ulonglong2*>(g_Qtab + qrow);
#pragma unroll
        for (int j = 0; j < 8; j++) {
            ulonglong2 a = q4[j];
            q2[2 * j]     = a.x;
            q2[2 * j + 1] = a.y;
        }
    }
    // k, v rows into shared (own row; padded ls stride)
    {
        const float4* k4 = reinterpret_cast<const float4*>(g_Ktab + qrow);
        const float4* v4 = reinterpret_cast<const float4*>(g_Vtab + qrow);
        float4* skd = reinterpret_cast<float4*>(s_un + ls * KV_LS_STRIDE + t * 32);
        float4* svd = reinterpret_cast<float4*>(s_un + 4224 + ls * KV_LS_STRIDE + t * 32);
#pragma unroll
        for (int j = 0; j < 8; j++) { skd[j] = k4[j]; svd[j] = v4[j]; }
    }
    __syncthreads();

    // ----- attention scores: sc[h][s] = SQRT_C * q_h . k_h(s), causal -----
    float sc[4][8];
    const float* kbase = s_un + ls * KV_LS_STRIDE;
#pragma unroll
    for (int s = 0; s < 8; s++) {
        const ulonglong2* kr = reinterpret_cast<const ulonglong2*>(kbase + s * 32);
#pragma unroll
        for (int h = 0; h < 4; h++) {
            ulonglong2 a = kr[2 * h];
            ulonglong2 b = kr[2 * h + 1];
            u64 acc0 = 0ull, acc1 = 0ull;         // two chains
            acc0 = fma2(q2[4 * h + 0], a.x, acc0);
            acc1 = fma2(q2[4 * h + 1], a.y, acc1);
            acc0 = fma2(q2[4 * h + 2], b.x, acc0);
            acc1 = fma2(q2[4 * h + 3], b.y, acc1);
            float dh = hadd2(acc0) + hadd2(acc1);
            sc[h][s] = (s <= t) ? dh * SQRT_C : -1e30f;
        }
    }

    // ----- softmax per head -----
    float rinv[4];
#pragma unroll
    for (int h = 0; h < 4; h++) {
        float m = sc[h][0];
#pragma unroll
        for (int s = 1; s < 8; s++) m = fmaxf(m, sc[h][s]);
        float sum = 0.f;
#pragma unroll
        for (int s = 0; s < 8; s++) {
            float e = __expf(sc[h][s] - m);   // masked lanes underflow to 0
            sc[h][s] = e;
            sum += e;
        }
        rinv[h] = __fdividef(1.0f, sum);
    }

    // ----- out = softmax @ V (concat heads), packed pairs along d -----
    u64 outv2[16];
#pragma unroll
    for (int j = 0; j < 16; j++) outv2[j] = 0ull;
    const float* vbase = s_un + 4224 + ls * KV_LS_STRIDE;
#pragma unroll
    for (int s = 0; s < 8; s++) {
        const ulonglong2* vr = reinterpret_cast<const ulonglong2*>(vbase + s * 32);
#pragma unroll
        for (int h = 0; h < 4; h++) {
            float p = sc[h][s] * rinv[h];        // 0 for masked s
            u64 p2 = pack2(p, p);
            ulonglong2 a = vr[2 * h];
            ulonglong2 b = vr[2 * h + 1];
            outv2[4 * h + 0] = fma2(p2, a.x, outv2[4 * h + 0]);
            outv2[4 * h + 1] = fma2(p2, a.y, outv2[4 * h + 1]);
            outv2[4 * h + 2] = fma2(p2, b.x, outv2[4 * h + 2]);
            outv2[4 * h + 3] = fma2(p2, b.y, outv2[4 * h + 3]);
        }
    }
    // unpack attention output to scalars (register-pair aliasing, ~free)
    float ov[32];
#pragma unroll
    for (int j = 0; j < 16; j++) { ov[2 * j] = lo2(outv2[j]); ov[2 * j + 1] = hi2(outv2[j]); }
    __syncthreads();   // done reading K/V -> union becomes logits stage

    // ----- MLP: y = relu(ov @ Wmlp + b); weights from CONSTANT port -----
    u64 macc[16];
#pragma unroll
    for (int j = 0; j < 16; j++) macc[j] = ldc2(c_bmlp + 2 * j);
#pragma unroll
    for (int c = 0; c < 32; c++) {
        u64 xb = pack2(ov[c], ov[c]);
#pragma unroll
        for (int jj = 0; jj < 16; jj++)
            macc[jj] = fma2(xb, ldc2(c_wmlp + c * 32 + 2 * jj), macc[jj]);
    }
    float y[32];
#pragma unroll
    for (int j = 0; j < 16; j++) {
        y[2 * j]     = fmaxf(lo2(macc[j]), 0.f);
        y[2 * j + 1] = fmaxf(hi2(macc[j]), 0.f);
    }

    // ----- lm-head: logits packed along vocab (constant weights); online LSE -
    float* stagerow = s_un + tid * 65;          // dense stage = output layout
    float m = -1e30f, sum = 0.f;

#pragma unroll
    for (int chunk = 0; chunk < 4; chunk++) {      // vocab [16*chunk, 16*chunk+16)
        const int vb = chunk * 16;
        u64 acc[8];
#pragma unroll
        for (int p = 0; p < 8; p++) acc[p] = ldc2(c_blm + vb + 2 * p);
#pragma unroll
        for (int c = 0; c < 32; c++) {
            u64 yb = pack2(y[c], y[c]);
            const float* wr = c_wlm + c * WLM_STRIDE + vb;
#pragma unroll
            for (int p = 0; p < 8; p++)
                acc[p] = fma2(yb, ldc2(wr + 2 * p), acc[p]);
        }
        // store + online LSE over these 16 logits
        float cm = -1e30f;
        float l[16];
#pragma unroll
        for (int p = 0; p < 8; p++) {
            l[2 * p] = lo2(acc[p]); l[2 * p + 1] = hi2(acc[p]);
            stagerow[vb + 2 * p]     = l[2 * p];
            stagerow[vb + 2 * p + 1] = l[2 * p + 1];
            cm = fmaxf(cm, fmaxf(l[2 * p], l[2 * p + 1]));
        }
        float mn = fmaxf(m, cm);
        float s2 = sum * __expf(m - mn);
#pragma unroll
        for (int p = 0; p < 16; p++) s2 += __expf(l[p] - mn);
        m = mn; sum = s2;
    }
    {   // epilogue: v = 64 (pair partner v=65 is a zero pad, ignored)
        u64 acc = ldc2(c_blm + 64);
#pragma unroll
        for (int c = 0; c < 32; c++) {
            u64 yb = pack2(y[c], y[c]);
            acc = fma2(yb, ldc2(c_wlm + c * WLM_STRIDE + 64), acc);
        }
        float l64 = lo2(acc);
        stagerow[64] = l64;
        float mn = fmaxf(m, l64);
        sum = sum * __expf(m - mn) + __expf(l64 - mn);
        m = mn;
    }
    float ltgt  = stagerow[tgtv];              // own row, no sync needed
    float lossi = (m + __logf(sum)) - ltgt;

    // warp then block reduce, one atomic per block; last block writes mean
#pragma unroll
    for (int off = 16; off > 0; off >>= 1)
        lossi += __shfl_down_sync(0xffffffffu, lossi, off);
    if ((tid & 31) == 0) s_lred[tid >> 5] = lossi;
    __syncthreads();    // also guarantees stage[] fully written for flush
    if (tid == 0) {
        atomicAdd(&g_loss, s_lred[0] + s_lred[1] + s_lred[2] + s_lred[3]);
        __threadfence();
        unsigned prev = atomicAdd(&g_done, 1u);
        if ((int)prev == nblocks - 1 && loss_idx >= 0)
            out[loss_idx] = g_loss * inv_n;
    }

    // ----- coalesced flush: dense stage -> 2080 float4 per block -----
    if (write_logits) {
        float4* o4 = reinterpret_cast<float4*>(out) + (size_t)blockIdx.x * 2080;
        const float4* st4 = reinterpret_cast<const float4*>(s_un);
        for (int i = tid; i < 2080; i += 128) o4[i] = st4[i];
    }
}

extern "C" void kernel_launch(void* const* d_in, const int* in_sizes, int n_in,
                              void* d_out, int out_size) {
    const int*   idx     = (const int*)d_in[0];
    const int*   targets = (const int*)d_in[1];
    const float* tok_emb = (const float*)d_in[2];
    const float* pos_emb = (const float*)d_in[3];
    const float* Wq      = (const float*)d_in[4];
    const float* Wk      = (const float*)d_in[5];
    const float* Wv      = (const float*)d_in[6];
    const float* Wmlp    = (const float*)d_in[7];
    const float* bmlp    = (const float*)d_in[8];
    const float* Wlm     = (const float*)d_in[9];
    const float* blm     = (const float*)d_in[10];
    float* out = (float*)d_out;

    const long nrows = in_sizes[0];           // B*T = 524288
    const long total = nrows * VOCAB;         // logits element count
    int write_logits = ((long)out_size >= total) ? 1 : 0;
    int loss_idx = -1;
    if ((long)out_size == total + 1) loss_idx = (int)total;
    else if (out_size == 1)          { loss_idx = 0; write_logits = 0; }

    // Stage weights into constant memory (async D2D; graph-capturable)
    cudaMemcpyToSymbolAsync(c_wmlp, Wmlp, 32 * 32 * sizeof(float), 0,
                            cudaMemcpyDeviceToDevice);
    cudaMemcpyToSymbolAsync(c_bmlp, bmlp, 32 * sizeof(float), 0,
                            cudaMemcpyDeviceToDevice);
    cudaMemcpyToSymbolAsync(c_blm,  blm,  65 * sizeof(float), 0,
                            cudaMemcpyDeviceToDevice);
    {   // Wlm [32][65] -> padded [32][68] via pitched D2D copy
        void* sym = nullptr;
        cudaGetSymbolAddress(&sym, c_wlm);
        cudaMemcpy2DAsync(sym, WLM_STRIDE * sizeof(float),
                          Wlm, 65 * sizeof(float),
                          65 * sizeof(float), 32, cudaMemcpyDeviceToDevice);
    }

    int nblocks = (int)(nrows / 128);
    k_tables<<<(520 * 32 + 255) / 256, 256>>>(tok_emb, pos_emb, Wq, Wk, Wv);
    k_main<<<nblocks, 128>>>(idx, targets, out, write_logits, loss_idx,
                             1.0f / (float)nrows, nblocks);
}

// round 5
// speedup vs baseline: 1.2782x; 1.0545x over previous
#include <cuda_runtime.h>

typedef unsigned long long u64;

#define VOCAB   65
#define SQRT_C  5.656854249492381f   // faithful bug: scores MULTIPLIED by sqrt(32)

// ---------------- scratch (device globals; no allocations allowed) ----------
__device__ __align__(16) float g_Qtab[520 * 32];
__device__ __align__(16) float g_Ktab[520 * 32];
__device__ __align__(16) float g_Vtab[520 * 32];
__device__ float    g_loss;
__device__ unsigned g_done;

// ---------------- packed weights: one constant block, one memcpy ------------
#define WLM_STRIDE 68          // padded vocab row stride (16B-aligned rows)
#define OFF_WMLP   0           // [c][c2]    1024 floats
#define OFF_BMLP   1024        //            32
#define OFF_BLM    1056        //            68 (65 + pad)
#define OFF_WLM    1124        // [c][v]     32*68 = 2176 (byte off 4496, 16B-aligned)
#define PACK_N     3300
__device__   __align__(16) float g_pack[PACK_N];
__constant__ __align__(16) float c_all[PACK_N];

// ---------------- packed f32x2 helpers (sm_103a) ----------------------------
__device__ __forceinline__ u64 fma2(u64 a, u64 b, u64 c) {
    u64 d;
    asm("fma.rn.f32x2 %0, %1, %2, %3;" : "=l"(d) : "l"(a), "l"(b), "l"(c));
    return d;
}
__device__ __forceinline__ float hadd2(u64 a) {
    float lo, hi;
    asm("mov.b64 {%0,%1}, %2;" : "=f"(lo), "=f"(hi) : "l"(a));
    return lo + hi;
}
__device__ __forceinline__ u64 pack2(float lo, float hi) {
    u64 r;
    asm("mov.b64 %0, {%1,%2};" : "=l"(r) : "f"(lo), "f"(hi));
    return r;
}
__device__ __forceinline__ float lo2(u64 a) {
    float lo, hi;
    asm("mov.b64 {%0,%1}, %2;" : "=f"(lo), "=f"(hi) : "l"(a));
    return lo;
}
__device__ __forceinline__ float hi2(u64 a) {
    float lo, hi;
    asm("mov.b64 {%0,%1}, %2;" : "=f"(lo), "=f"(hi) : "l"(a));
    return hi;
}
__device__ __forceinline__ u64 ldc2(const float* p) {        // 8B constant load
    return *reinterpret_cast<const u64*>(p);
}
__device__ __forceinline__ ulonglong2 ldc4(const float* p) { // 16B constant load
    return *reinterpret_cast<const ulonglong2*>(p);
}

// Precompute Q/K/V tables AND pack weights for the single constant upload.
__global__ void k_tables(const float* __restrict__ tok_emb,
                         const float* __restrict__ pos_emb,
                         const float* __restrict__ Wq,
                         const float* __restrict__ Wk,
                         const float* __restrict__ Wv,
                         const float* __restrict__ Wmlp,
                         const float* __restrict__ bmlp,
                         const float* __restrict__ Wlm,
                         const float* __restrict__ blm) {
    int i = blockIdx.x * blockDim.x + threadIdx.x;
    if (i == 0) { g_loss = 0.0f; g_done = 0u; }
    if (i < 520 * 32) {
        int row = i >> 5;          // t*65 + tok
        int c   = i & 31;          // h*8 + d
        int t   = row / 65;
        int tok = row % 65;
        int h   = c >> 3;
        int d   = c & 7;
        float aq = 0.f, ak = 0.f, av = 0.f;
#pragma unroll
        for (int cc = 0; cc < 32; cc++) {
            float xv = tok_emb[tok * 32 + cc] + pos_emb[t * 32 + cc];
            int wi = h * 256 + cc * 8 + d;
            aq = fmaf(xv, Wq[wi], aq);
            ak = fmaf(xv, Wk[wi], ak);
            av = fmaf(xv, Wv[wi], av);
        }
        g_Qtab[i] = aq;
        g_Ktab[i] = ak;
        g_Vtab[i] = av;
    } else {
        int i2 = i - 520 * 32;
        if (i2 < PACK_N) {
            float v;
            if (i2 < OFF_BMLP)                 v = Wmlp[i2];
            else if (i2 < OFF_BLM)             v = bmlp[i2 - OFF_BMLP];
            else if (i2 < OFF_WLM) {
                int j = i2 - OFF_BLM;
                v = (j < 65) ? blm[j] : 0.0f;
            } else {
                int j  = i2 - OFF_WLM;
                int c  = j / WLM_STRIDE;
                int vv = j - c * WLM_STRIDE;
                v = (vv < 65) ? Wlm[c * 65 + vv] : 0.0f;
            }
            g_pack[i2] = v;
        }
    }
}

#define KV_LS_STRIDE 264   // floats per sequence: +8 banks per ls -> conflict-free

// Main fused kernel: one thread per (sequence, token). 128 threads = 16 seqs.
__global__ __launch_bounds__(128, 4)
void k_main(const int* __restrict__ idx, const int* __restrict__ tgt,
            float* __restrict__ out, int write_logits,
            int loss_idx, float inv_n, int nblocks) {
    // union: K at [ls*264+s*32], V at [4224+...]; later logits stage [128][65] dense
    __shared__ __align__(16) float s_un[8448];
    __shared__ float               s_lred[4];

    const float* c_wmlp = c_all + OFF_WMLP;
    const float* c_bmlp = c_all + OFF_BMLP;
    const float* c_blm  = c_all + OFF_BLM;
    const float* c_wlm  = c_all + OFF_WLM;

    const int tid  = threadIdx.x;
    const int ls   = tid >> 3;                 // local sequence 0..15
    const int t    = tid & 7;                  // token position
    const int rowg = blockIdx.x * 128 + tid;   // global token row
    const int tok  = idx[rowg];
    const int tgtv = tgt[rowg];
    const int qrow = (t * 65 + tok) * 32;

    // q into packed registers: q2[j] = (q[2j], q[2j+1])
    u64 q2[16];
    {
        const ulonglong2* q4 = reinterpret_cast<const ulonglong2*>(g_Qtab + qrow);
#pragma unroll
        for (int j = 0; j < 8; j++) {
            ulonglong2 a = q4[j];
            q2[2 * j]     = a.x;
            q2[2 * j + 1] = a.y;
        }
    }
    // k, v rows into shared (own row; padded ls stride)
    {
        const float4* k4 = reinterpret_cast<const float4*>(g_Ktab + qrow);
        const float4* v4 = reinterpret_cast<const float4*>(g_Vtab + qrow);
        float4* skd = reinterpret_cast<float4*>(s_un + ls * KV_LS_STRIDE + t * 32);
        float4* svd = reinterpret_cast<float4*>(s_un + 4224 + ls * KV_LS_STRIDE + t * 32);
#pragma unroll
        for (int j = 0; j < 8; j++) { skd[j] = k4[j]; svd[j] = v4[j]; }
    }
    __syncthreads();

    // ----- attention scores: sc[h][s] = SQRT_C * q_h . k_h(s), causal -----
    float sc[4][8];
    const float* kbase = s_un + ls * KV_LS_STRIDE;
#pragma unroll
    for (int s = 0; s < 8; s++) {
        const ulonglong2* kr = reinterpret_cast<const ulonglong2*>(kbase + s * 32);
#pragma unroll
        for (int h = 0; h < 4; h++) {
            ulonglong2 a = kr[2 * h];
            ulonglong2 b = kr[2 * h + 1];
            u64 acc0 = 0ull, acc1 = 0ull;         // two chains
            acc0 = fma2(q2[4 * h + 0], a.x, acc0);
            acc1 = fma2(q2[4 * h + 1], a.y, acc1);
            acc0 = fma2(q2[4 * h + 2], b.x, acc0);
            acc1 = fma2(q2[4 * h + 3], b.y, acc1);
            float dh = hadd2(acc0) + hadd2(acc1);
            sc[h][s] = (s <= t) ? dh * SQRT_C : -1e30f;
        }
    }

    // ----- softmax per head -----
    float rinv[4];
#pragma unroll
    for (int h = 0; h < 4; h++) {
        float m = sc[h][0];
#pragma unroll
        for (int s = 1; s < 8; s++) m = fmaxf(m, sc[h][s]);
        float sum = 0.f;
#pragma unroll
        for (int s = 0; s < 8; s++) {
            float e = __expf(sc[h][s] - m);   // masked lanes underflow to 0
            sc[h][s] = e;
            sum += e;
        }
        rinv[h] = __fdividef(1.0f, sum);
    }

    // ----- out = softmax @ V (concat heads), packed pairs along d -----
    u64 outv2[16];
#pragma unroll
    for (int j = 0; j < 16; j++) outv2[j] = 0ull;
    const float* vbase = s_un + 4224 + ls * KV_LS_STRIDE;
#pragma unroll
    for (int s = 0; s < 8; s++) {
        const ulonglong2* vr = reinterpret_cast<const ulonglong2*>(vbase + s * 32);
#pragma unroll
        for (int h = 0; h < 4; h++) {
            float p = sc[h][s] * rinv[h];        // 0 for masked s
            u64 p2 = pack2(p, p);
            ulonglong2 a = vr[2 * h];
            ulonglong2 b = vr[2 * h + 1];
            outv2[4 * h + 0] = fma2(p2, a.x, outv2[4 * h + 0]);
            outv2[4 * h + 1] = fma2(p2, a.y, outv2[4 * h + 1]);
            outv2[4 * h + 2] = fma2(p2, b.x, outv2[4 * h + 2]);
            outv2[4 * h + 3] = fma2(p2, b.y, outv2[4 * h + 3]);
        }
    }
    // unpack attention output to scalars (register-pair aliasing, ~free)
    float ov[32];
#pragma unroll
    for (int j = 0; j < 16; j++) { ov[2 * j] = lo2(outv2[j]); ov[2 * j + 1] = hi2(outv2[j]); }
    __syncthreads();   // done reading K/V -> union becomes logits stage

    // ----- MLP: y = relu(ov @ Wmlp + b); 16B constant loads -----
    u64 macc[16];
#pragma unroll
    for (int j = 0; j < 8; j++) {
        ulonglong2 b = ldc4(c_bmlp + 4 * j);
        macc[2 * j] = b.x; macc[2 * j + 1] = b.y;
    }
#pragma unroll
    for (int c = 0; c < 32; c++) {
        u64 xb = pack2(ov[c], ov[c]);
#pragma unroll
        for (int jj = 0; jj < 8; jj++) {
            ulonglong2 w = ldc4(c_wmlp + c * 32 + 4 * jj);
            macc[2 * jj]     = fma2(xb, w.x, macc[2 * jj]);
            macc[2 * jj + 1] = fma2(xb, w.y, macc[2 * jj + 1]);
        }
    }
    float y[32];
#pragma unroll
    for (int j = 0; j < 16; j++) {
        y[2 * j]     = fmaxf(lo2(macc[j]), 0.f);
        y[2 * j + 1] = fmaxf(hi2(macc[j]), 0.f);
    }

    // ----- lm-head: 16 logits per chunk; 16B constant loads; online LSE -----
    float* stagerow = s_un + tid * 65;          // dense stage = output layout
    float m = -1e30f, sum = 0.f;

#pragma unroll
    for (int chunk = 0; chunk < 4; chunk++) {      // vocab [16*chunk, 16*chunk+16)
        const int vb = chunk * 16;
        u64 acc[8];
#pragma unroll
        for (int p = 0; p < 4; p++) {
            ulonglong2 b = ldc4(c_blm + vb + 4 * p);
            acc[2 * p] = b.x; acc[2 * p + 1] = b.y;
        }
#pragma unroll
        for (int c = 0; c < 32; c++) {
            u64 yb = pack2(y[c], y[c]);
            const float* wr = c_wlm + c * WLM_STRIDE + vb;
#pragma unroll
            for (int q = 0; q < 4; q++) {
                ulonglong2 w = ldc4(wr + 4 * q);
                acc[2 * q]     = fma2(yb, w.x, acc[2 * q]);
                acc[2 * q + 1] = fma2(yb, w.y, acc[2 * q + 1]);
            }
        }
        // store + online LSE over these 16 logits
        float cm = -1e30f;
        float l[16];
#pragma unroll
        for (int p = 0; p < 8; p++) {
            l[2 * p] = lo2(acc[p]); l[2 * p + 1] = hi2(acc[p]);
            stagerow[vb + 2 * p]     = l[2 * p];
            stagerow[vb + 2 * p + 1] = l[2 * p + 1];
            cm = fmaxf(cm, fmaxf(l[2 * p], l[2 * p + 1]));
        }
        float mn = fmaxf(m, cm);
        float s2 = sum * __expf(m - mn);
#pragma unroll
        for (int p = 0; p < 16; p++) s2 += __expf(l[p] - mn);
        m = mn; sum = s2;
    }
    {   // epilogue: v = 64 (pair partner v=65 is a zero pad, ignored)
        u64 acc = ldc2(c_blm + 64);
#pragma unroll
        for (int c = 0; c < 32; c++) {
            u64 yb = pack2(y[c], y[c]);
            acc = fma2(yb, ldc2(c_wlm + c * WLM_STRIDE + 64), acc);
        }
        float l64 = lo2(acc);
        stagerow[64] = l64;
        float mn = fmaxf(m, l64);
        sum = sum * __expf(m - mn) + __expf(l64 - mn);
        m = mn;
    }
    float ltgt  = stagerow[tgtv];              // own row, no sync needed
    float lossi = (m + __logf(sum)) - ltgt;

    // warp then block reduce, one atomic per block; last block writes mean
#pragma unroll
    for (int off = 16; off > 0; off >>= 1)
        lossi += __shfl_down_sync(0xffffffffu, lossi, off);
    if ((tid & 31) == 0) s_lred[tid >> 5] = lossi;
    __syncthreads();    // also guarantees stage[] fully written for the bulk store
    if (tid == 0) {
        atomicAdd(&g_loss, s_lred[0] + s_lred[1] + s_lred[2] + s_lred[3]);
        __threadfence();
        unsigned prev = atomicAdd(&g_done, 1u);
        if ((int)prev == nblocks - 1 && loss_idx >= 0)
            out[loss_idx] = g_loss * inv_n;
    }

    // ----- single TMA bulk store: SMEM stage -> GMEM logits (33280 B) -----
    if (write_logits && tid == 0) {
        unsigned int saddr;
        asm("{ .reg .u64 tmp; cvta.to.shared.u64 tmp, %1; cvt.u32.u64 %0, tmp; }"
            : "=r"(saddr) : "l"(s_un));
        const float* gdst = out + (size_t)blockIdx.x * 8320;
        asm volatile("fence.proxy.async.shared::cta;" ::: "memory");
        asm volatile("cp.async.bulk.global.shared::cta.bulk_group [%0], [%1], %2;"
                     :: "l"(gdst), "r"(saddr), "r"(33280) : "memory");
        asm volatile("cp.async.bulk.commit_group;" ::: "memory");
        asm volatile("cp.async.bulk.wait_group.read 0;" ::: "memory");
    }
}

extern "C" void kernel_launch(void* const* d_in, const int* in_sizes, int n_in,
                              void* d_out, int out_size) {
    const int*   idx     = (const int*)d_in[0];
    const int*   targets = (const int*)d_in[1];
    const float* tok_emb = (const float*)d_in[2];
    const float* pos_emb = (const float*)d_in[3];
    const float* Wq      = (const float*)d_in[4];
    const float* Wk      = (const float*)d_in[5];
    const float* Wv      = (const float*)d_in[6];
    const float* Wmlp    = (const float*)d_in[7];
    const float* bmlp    = (const float*)d_in[8];
    const float* Wlm     = (const float*)d_in[9];
    const float* blm     = (const float*)d_in[10];
    float* out = (float*)d_out;

    const long nrows = in_sizes[0];           // B*T = 524288
    const long total = nrows * VOCAB;         // logits element count
    int write_logits = ((long)out_size >= total) ? 1 : 0;
    int loss_idx = -1;
    if ((long)out_size == total + 1) loss_idx = (int)total;
    else if (out_size == 1)          { loss_idx = 0; write_logits = 0; }

    // Tables + weight packing, then ONE constant upload (D2D, capturable)
    int work = 520 * 32 + PACK_N;
    k_tables<<<(work + 255) / 256, 256>>>(tok_emb, pos_emb, Wq, Wk, Wv,
                                          Wmlp, bmlp, Wlm, blm);
    {
        void* src = nullptr;
        cudaGetSymbolAddress(&src, g_pack);
        cudaMemcpyToSymbolAsync(c_all, src, PACK_N * sizeof(float), 0,
                                cudaMemcpyDeviceToDevice);
    }

    int nblocks = (int)(nrows / 128);
    k_main<<<nblocks, 128>>>(idx, targets, out, write_logits, loss_idx,
                             1.0f / (float)nrows, nblocks);
}

// round 6
// speedup vs baseline: 1.3257x; 1.0371x over previous
#include <cuda_runtime.h>

typedef unsigned long long u64;

#define VOCAB   65
#define SQRT_C  5.656854249492381f   // faithful bug: scores MULTIPLIED by sqrt(32)

// ---------------- scratch (device globals; no allocations allowed) ----------
__device__ __align__(16) float g_Qtab[520 * 32];
__device__ __align__(16) float g_Ktab[520 * 32];   // pre-scaled by SQRT_C
__device__ __align__(16) float g_Vtab[520 * 32];
__device__ float    g_loss;
__device__ unsigned g_done;

// ---------------- packed weights: one constant block, one memcpy ------------
#define WLM_STRIDE 68          // padded vocab row stride (16B-aligned rows)
#define OFF_WMLP   0           // [c][c2]    1024 floats
#define OFF_BMLP   1024        //            32
#define OFF_BLM    1056        //            68 (65 + pad)
#define OFF_WLM    1124        // [c][v]     32*68 = 2176
#define PACK_N     3300
__device__   __align__(16) float g_pack[PACK_N];
__constant__ __align__(16) float c_all[PACK_N];

// ---------------- packed f32x2 helpers (sm_103a) ----------------------------
__device__ __forceinline__ u64 fma2(u64 a, u64 b, u64 c) {
    u64 d;
    asm("fma.rn.f32x2 %0, %1, %2, %3;" : "=l"(d) : "l"(a), "l"(b), "l"(c));
    return d;
}
__device__ __forceinline__ u64 add2(u64 a, u64 b) {
    u64 d;
    asm("add.rn.f32x2 %0, %1, %2;" : "=l"(d) : "l"(a), "l"(b));
    return d;
}
__device__ __forceinline__ float hadd2(u64 a) {
    float lo, hi;
    asm("mov.b64 {%0,%1}, %2;" : "=f"(lo), "=f"(hi) : "l"(a));
    return lo + hi;
}
__device__ __forceinline__ u64 pack2(float lo, float hi) {
    u64 r;
    asm("mov.b64 %0, {%1,%2};" : "=l"(r) : "f"(lo), "f"(hi));
    return r;
}
__device__ __forceinline__ float lo2(u64 a) {
    float lo, hi;
    asm("mov.b64 {%0,%1}, %2;" : "=f"(lo), "=f"(hi) : "l"(a));
    return lo;
}
__device__ __forceinline__ float hi2(u64 a) {
    float lo, hi;
    asm("mov.b64 {%0,%1}, %2;" : "=f"(lo), "=f"(hi) : "l"(a));
    return hi;
}
__device__ __forceinline__ u64 ldc2(const float* p) {        // 8B constant load
    return *reinterpret_cast<const u64*>(p);
}
__device__ __forceinline__ ulonglong2 ldc4(const float* p) { // 16B constant load
    return *reinterpret_cast<const ulonglong2*>(p);
}

// Precompute Q/K/V tables AND pack weights for the single constant upload.
__global__ void k_tables(const float* __restrict__ tok_emb,
                         const float* __restrict__ pos_emb,
                         const float* __restrict__ Wq,
                         const float* __restrict__ Wk,
                         const float* __restrict__ Wv,
                         const float* __restrict__ Wmlp,
                         const float* __restrict__ bmlp,
                         const float* __restrict__ Wlm,
                         const float* __restrict__ blm) {
    int i = blockIdx.x * blockDim.x + threadIdx.x;
    if (i == 0) { g_loss = 0.0f; g_done = 0u; }
    if (i < 520 * 32) {
        int row = i >> 5;          // t*65 + tok
        int c   = i & 31;          // h*8 + d
        int t   = row / 65;
        int tok = row % 65;
        int h   = c >> 3;
        int d   = c & 7;
        float aq = 0.f, ak = 0.f, av = 0.f;
#pragma unroll
        for (int cc = 0; cc < 32; cc++) {
            float xv = tok_emb[tok * 32 + cc] + pos_emb[t * 32 + cc];
            int wi = h * 256 + cc * 8 + d;
            aq = fmaf(xv, Wq[wi], aq);
            ak = fmaf(xv, Wk[wi], ak);
            av = fmaf(xv, Wv[wi], av);
        }
        g_Qtab[i] = aq;
        g_Ktab[i] = ak * SQRT_C;   // fold score scale into K
        g_Vtab[i] = av;
    } else {
        int i2 = i - 520 * 32;
        if (i2 < PACK_N) {
            float v;
            if (i2 < OFF_BMLP)                 v = Wmlp[i2];
            else if (i2 < OFF_BLM)             v = bmlp[i2 - OFF_BMLP];
            else if (i2 < OFF_WLM) {
                int j = i2 - OFF_BLM;
                v = (j < 65) ? blm[j] : 0.0f;
            } else {
                int j  = i2 - OFF_WLM;
                int c  = j / WLM_STRIDE;
                int vv = j - c * WLM_STRIDE;
                v = (vv < 65) ? Wlm[c * 65 + vv] : 0.0f;
            }
            g_pack[i2] = v;
        }
    }
}

#define KV_LS_STRIDE 264   // floats per sequence: +8 banks per ls -> conflict-free

// Main fused kernel: one thread per (sequence, token). 128 threads = 16 seqs.
// 6 CTAs/SM target (85-reg cap) — attention done in head-pairs to fit.
__global__ __launch_bounds__(128, 6)
void k_main(const int* __restrict__ idx, const int* __restrict__ tgt,
            float* __restrict__ out, int write_logits,
            int loss_idx, float inv_n, int nblocks) {
    // union: K at [ls*264+s*32], V at [4224+...]; later logits stage [128][65] dense
    __shared__ __align__(16) float s_un[8448];
    __shared__ float               s_lred[4];

    const float* c_wmlp = c_all + OFF_WMLP;
    const float* c_bmlp = c_all + OFF_BMLP;
    const float* c_blm  = c_all + OFF_BLM;
    const float* c_wlm  = c_all + OFF_WLM;

    const int tid  = threadIdx.x;
    const int ls   = tid >> 3;                 // local sequence 0..15
    const int t    = tid & 7;                  // token position
    const int rowg = blockIdx.x * 128 + tid;   // global token row
    const int tok  = idx[rowg];
    const int tgtv = tgt[rowg];
    const int qrow = (t * 65 + tok) * 32;

    // k, v rows into shared (own row; padded ls stride)
    {
        const float4* k4 = reinterpret_cast<const float4*>(g_Ktab + qrow);
        const float4* v4 = reinterpret_cast<const float4*>(g_Vtab + qrow);
        float4* skd = reinterpret_cast<float4*>(s_un + ls * KV_LS_STRIDE + t * 32);
        float4* svd = reinterpret_cast<float4*>(s_un + 4224 + ls * KV_LS_STRIDE + t * 32);
#pragma unroll
        for (int j = 0; j < 8; j++) { skd[j] = k4[j]; svd[j] = v4[j]; }
    }
    __syncthreads();

    // ----- attention in head-pairs (hp = heads {2hp, 2hp+1}) -----
    float ov[32];
#pragma unroll
    for (int hp = 0; hp < 2; hp++) {
        // q for this head-pair: 16 floats = 8 packed u64
        u64 q2[8];
        {
            const ulonglong2* q4 =
                reinterpret_cast<const ulonglong2*>(g_Qtab + qrow + hp * 16);
#pragma unroll
            for (int j = 0; j < 4; j++) {
                ulonglong2 a = q4[j];
                q2[2 * j] = a.x; q2[2 * j + 1] = a.y;
            }
        }
        // scores (K pre-scaled by SQRT_C)
        float sc[2][8];
        const float* kb = s_un + ls * KV_LS_STRIDE + hp * 16;
#pragma unroll
        for (int s = 0; s < 8; s++) {
            const ulonglong2* kr = reinterpret_cast<const ulonglong2*>(kb + s * 32);
            ulonglong2 a = kr[0], b = kr[1], c = kr[2], d = kr[3];
            u64 e0 = 0ull, e1 = 0ull, f0 = 0ull, f1 = 0ull;
            e0 = fma2(q2[0], a.x, e0); e1 = fma2(q2[1], a.y, e1);
            e0 = fma2(q2[2], b.x, e0); e1 = fma2(q2[3], b.y, e1);
            f0 = fma2(q2[4], c.x, f0); f1 = fma2(q2[5], c.y, f1);
            f0 = fma2(q2[6], d.x, f0); f1 = fma2(q2[7], d.y, f1);
            float se = hadd2(add2(e0, e1));
            float sf = hadd2(add2(f0, f1));
            sc[0][s] = (s <= t) ? se : -1e30f;
            sc[1][s] = (s <= t) ? sf : -1e30f;
        }
        // softmax for the 2 heads
        float rinv[2];
#pragma unroll
        for (int hh = 0; hh < 2; hh++) {
            float m = sc[hh][0];
#pragma unroll
            for (int s = 1; s < 8; s++) m = fmaxf(m, sc[hh][s]);
            float sum = 0.f;
#pragma unroll
            for (int s = 0; s < 8; s++) {
                float e = __expf(sc[hh][s] - m);   // masked lanes underflow to 0
                sc[hh][s] = e;
                sum += e;
            }
            rinv[hh] = __fdividef(1.0f, sum);
        }
        // out = softmax @ V for the 2 heads
        u64 oacc[8];
#pragma unroll
        for (int j = 0; j < 8; j++) oacc[j] = 0ull;
        const float* vb = s_un + 4224 + ls * KV_LS_STRIDE + hp * 16;
#pragma unroll
        for (int s = 0; s < 8; s++) {
            const ulonglong2* vr = reinterpret_cast<const ulonglong2*>(vb + s * 32);
            ulonglong2 a = vr[0], b = vr[1], c = vr[2], d = vr[3];
            float p0 = sc[0][s] * rinv[0];
            float p1 = sc[1][s] * rinv[1];
            u64 p02 = pack2(p0, p0), p12 = pack2(p1, p1);
            oacc[0] = fma2(p02, a.x, oacc[0]); oacc[1] = fma2(p02, a.y, oacc[1]);
            oacc[2] = fma2(p02, b.x, oacc[2]); oacc[3] = fma2(p02, b.y, oacc[3]);
            oacc[4] = fma2(p12, c.x, oacc[4]); oacc[5] = fma2(p12, c.y, oacc[5]);
            oacc[6] = fma2(p12, d.x, oacc[6]); oacc[7] = fma2(p12, d.y, oacc[7]);
        }
#pragma unroll
        for (int j = 0; j < 8; j++) {
            ov[hp * 16 + 2 * j]     = lo2(oacc[j]);
            ov[hp * 16 + 2 * j + 1] = hi2(oacc[j]);
        }
    }
    __syncthreads();   // done reading K/V -> union becomes logits stage

    // ----- MLP: y = relu(ov @ Wmlp + b); 16B constant loads -----
    u64 macc[16];
#pragma unroll
    for (int j = 0; j < 8; j++) {
        ulonglong2 b = ldc4(c_bmlp + 4 * j);
        macc[2 * j] = b.x; macc[2 * j + 1] = b.y;
    }
#pragma unroll
    for (int c = 0; c < 32; c++) {
        u64 xb = pack2(ov[c], ov[c]);
#pragma unroll
        for (int jj = 0; jj < 8; jj++) {
            ulonglong2 w = ldc4(c_wmlp + c * 32 + 4 * jj);
            macc[2 * jj]     = fma2(xb, w.x, macc[2 * jj]);
            macc[2 * jj + 1] = fma2(xb, w.y, macc[2 * jj + 1]);
        }
    }
    float y[32];
#pragma unroll
    for (int j = 0; j < 16; j++) {
        y[2 * j]     = fmaxf(lo2(macc[j]), 0.f);
        y[2 * j + 1] = fmaxf(hi2(macc[j]), 0.f);
    }

    // ----- lm-head: 16 logits per chunk; 16B constant loads; online LSE -----
    float* stagerow = s_un + tid * 65;          // dense stage = output layout
    float m = -1e30f, sum = 0.f;

#pragma unroll
    for (int chunk = 0; chunk < 4; chunk++) {      // vocab [16*chunk, 16*chunk+16)
        const int vb = chunk * 16;
        u64 acc[8];
#pragma unroll
        for (int p = 0; p < 4; p++) {
            ulonglong2 b = ldc4(c_blm + vb + 4 * p);
            acc[2 * p] = b.x; acc[2 * p + 1] = b.y;
        }
#pragma unroll
        for (int c = 0; c < 32; c++) {
            u64 yb = pack2(y[c], y[c]);
            const float* wr = c_wlm + c * WLM_STRIDE + vb;
#pragma unroll
            for (int q = 0; q < 4; q++) {
                ulonglong2 w = ldc4(wr + 4 * q);
                acc[2 * q]     = fma2(yb, w.x, acc[2 * q]);
                acc[2 * q + 1] = fma2(yb, w.y, acc[2 * q + 1]);
            }
        }
        // store + online LSE over these 16 logits
        float cm = -1e30f;
        float l[16];
#pragma unroll
        for (int p = 0; p < 8; p++) {
            l[2 * p] = lo2(acc[p]); l[2 * p + 1] = hi2(acc[p]);
            stagerow[vb + 2 * p]     = l[2 * p];
            stagerow[vb + 2 * p + 1] = l[2 * p + 1];
            cm = fmaxf(cm, fmaxf(l[2 * p], l[2 * p + 1]));
        }
        float mn = fmaxf(m, cm);
        float s2 = sum * __expf(m - mn);
#pragma unroll
        for (int p = 0; p < 16; p++) s2 += __expf(l[p] - mn);
        m = mn; sum = s2;
    }
    {   // epilogue: v = 64 (pair partner v=65 is a zero pad, ignored)
        u64 acc = ldc2(c_blm + 64);
#pragma unroll
        for (int c = 0; c < 32; c++) {
            u64 yb = pack2(y[c], y[c]);
            acc = fma2(yb, ldc2(c_wlm + c * WLM_STRIDE + 64), acc);
        }
        float l64 = lo2(acc);
        stagerow[64] = l64;
        float mn = fmaxf(m, l64);
        sum = sum * __expf(m - mn) + __expf(l64 - mn);
        m = mn;
    }
    float ltgt  = stagerow[tgtv];              // own row, no sync needed
    float lossi = (m + __logf(sum)) - ltgt;

    // warp then block reduce, one atomic per block; last block writes mean
#pragma unroll
    for (int off = 16; off > 0; off >>= 1)
        lossi += __shfl_down_sync(0xffffffffu, lossi, off);
    if ((tid & 31) == 0) s_lred[tid >> 5] = lossi;
    __syncthreads();    // also guarantees stage[] fully written for the bulk store
    if (tid == 0) {
        atomicAdd(&g_loss, s_lred[0] + s_lred[1] + s_lred[2] + s_lred[3]);
        __threadfence();
        unsigned prev = atomicAdd(&g_done, 1u);
        if ((int)prev == nblocks - 1 && loss_idx >= 0)
            out[loss_idx] = g_loss * inv_n;
    }

    // ----- single TMA bulk store: SMEM stage -> GMEM logits (33280 B) -----
    if (write_logits && tid == 0) {
        unsigned int saddr;
        asm("{ .reg .u64 tmp; cvta.to.shared.u64 tmp, %1; cvt.u32.u64 %0, tmp; }"
            : "=r"(saddr) : "l"(s_un));
        const float* gdst = out + (size_t)blockIdx.x * 8320;
        asm volatile("fence.proxy.async.shared::cta;" ::: "memory");
        asm volatile("cp.async.bulk.global.shared::cta.bulk_group [%0], [%1], %2;"
                     :: "l"(gdst), "r"(saddr), "r"(33280) : "memory");
        asm volatile("cp.async.bulk.commit_group;" ::: "memory");
        asm volatile("cp.async.bulk.wait_group.read 0;" ::: "memory");
    }
}

extern "C" void kernel_launch(void* const* d_in, const int* in_sizes, int n_in,
                              void* d_out, int out_size) {
    const int*   idx     = (const int*)d_in[0];
    const int*   targets = (const int*)d_in[1];
    const float* tok_emb = (const float*)d_in[2];
    const float* pos_emb = (const float*)d_in[3];
    const float* Wq      = (const float*)d_in[4];
    const float* Wk      = (const float*)d_in[5];
    const float* Wv      = (const float*)d_in[6];
    const float* Wmlp    = (const float*)d_in[7];
    const float* bmlp    = (const float*)d_in[8];
    const float* Wlm     = (const float*)d_in[9];
    const float* blm     = (const float*)d_in[10];
    float* out = (float*)d_out;

    const long nrows = in_sizes[0];           // B*T = 524288
    const long total = nrows * VOCAB;         // logits element count
    int write_logits = ((long)out_size >= total) ? 1 : 0;
    int loss_idx = -1;
    if ((long)out_size == total + 1) loss_idx = (int)total;
    else if (out_size == 1)          { loss_idx = 0; write_logits = 0; }

    // Tables + weight packing, then ONE constant upload (D2D, capturable)
    int work = 520 * 32 + PACK_N;
    k_tables<<<(work + 255) / 256, 256>>>(tok_emb, pos_emb, Wq, Wk, Wv,
                                          Wmlp, bmlp, Wlm, blm);
    {
        void* src = nullptr;
        cudaGetSymbolAddress(&src, g_pack);
        cudaMemcpyToSymbolAsync(c_all, src, PACK_N * sizeof(float), 0,
                                cudaMemcpyDeviceToDevice);
    }

    int nblocks = (int)(nrows / 128);
    k_main<<<nblocks, 128>>>(idx, targets, out, write_logits, loss_idx,
                             1.0f / (float)nrows, nblocks);
}

// round 7
// speedup vs baseline: 1.4152x; 1.0676x over previous
#include <cuda_runtime.h>

typedef unsigned long long u64;

#define VOCAB   65
#define SQRT_C  5.656854249492381f   // faithful bug: scores MULTIPLIED by sqrt(32)

// ---------------- scratch (device globals; no allocations allowed) ----------
__device__ __align__(16) float g_Qtab[520 * 32];
__device__ __align__(16) float g_Ktab[520 * 32];   // pre-scaled by SQRT_C
__device__ __align__(16) float g_Vtab[520 * 32];
__device__ float    g_loss;
__device__ unsigned g_done;

// ---------------- packed weights ---------------------------------------------
// g_pack/c_all layout: [Wmlp 1024][bmlp 32][blm 68][Wlm 32*68]
#define WLM_STRIDE 68          // padded vocab row stride (16B-aligned rows)
#define OFF_WMLP   0
#define OFF_BMLP   1024
#define OFF_BLM    1056        // byte off 4224, 16B-aligned
#define OFF_WLM    1124        // byte off 4496, 16B-aligned
#define PACK_N     3300
#define WB_N       2244        // blm(68) + wlm(2176), contiguous from OFF_BLM
__device__   __align__(16) float g_pack[PACK_N];
__constant__ __align__(16) float c_all[PACK_N];    // MLP weights read from here

// ---------------- packed f32x2 helpers (sm_103a) ----------------------------
__device__ __forceinline__ u64 fma2(u64 a, u64 b, u64 c) {
    u64 d;
    asm("fma.rn.f32x2 %0, %1, %2, %3;" : "=l"(d) : "l"(a), "l"(b), "l"(c));
    return d;
}
__device__ __forceinline__ u64 add2(u64 a, u64 b) {
    u64 d;
    asm("add.rn.f32x2 %0, %1, %2;" : "=l"(d) : "l"(a), "l"(b));
    return d;
}
__device__ __forceinline__ float hadd2(u64 a) {
    float lo, hi;
    asm("mov.b64 {%0,%1}, %2;" : "=f"(lo), "=f"(hi) : "l"(a));
    return lo + hi;
}
__device__ __forceinline__ u64 pack2(float lo, float hi) {
    u64 r;
    asm("mov.b64 %0, {%1,%2};" : "=l"(r) : "f"(lo), "f"(hi));
    return r;
}
__device__ __forceinline__ float lo2(u64 a) {
    float lo, hi;
    asm("mov.b64 {%0,%1}, %2;" : "=f"(lo), "=f"(hi) : "l"(a));
    return lo;
}
__device__ __forceinline__ float hi2(u64 a) {
    float lo, hi;
    asm("mov.b64 {%0,%1}, %2;" : "=f"(lo), "=f"(hi) : "l"(a));
    return hi;
}
__device__ __forceinline__ ulonglong2 ldc4(const float* p) { // 16B constant load
    return *reinterpret_cast<const ulonglong2*>(p);
}

// Precompute Q/K/V tables AND pack weights for the single constant upload.
__global__ void k_tables(const float* __restrict__ tok_emb,
                         const float* __restrict__ pos_emb,
                         const float* __restrict__ Wq,
                         const float* __restrict__ Wk,
                         const float* __restrict__ Wv,
                         const float* __restrict__ Wmlp,
                         const float* __restrict__ bmlp,
                         const float* __restrict__ Wlm,
                         const float* __restrict__ blm) {
    int i = blockIdx.x * blockDim.x + threadIdx.x;
    if (i == 0) { g_loss = 0.0f; g_done = 0u; }
    if (i < 520 * 32) {
        int row = i >> 5;          // t*65 + tok
        int c   = i & 31;          // h*8 + d
        int t   = row / 65;
        int tok = row % 65;
        int h   = c >> 3;
        int d   = c & 7;
        float aq = 0.f, ak = 0.f, av = 0.f;
#pragma unroll
        for (int cc = 0; cc < 32; cc++) {
            float xv = tok_emb[tok * 32 + cc] + pos_emb[t * 32 + cc];
            int wi = h * 256 + cc * 8 + d;
            aq = fmaf(xv, Wq[wi], aq);
            ak = fmaf(xv, Wk[wi], ak);
            av = fmaf(xv, Wv[wi], av);
        }
        g_Qtab[i] = aq;
        g_Ktab[i] = ak * SQRT_C;   // fold score scale into K
        g_Vtab[i] = av;
    } else {
        int i2 = i - 520 * 32;
        if (i2 < PACK_N) {
            float v;
            if (i2 < OFF_BMLP)                 v = Wmlp[i2];
            else if (i2 < OFF_BLM)             v = bmlp[i2 - OFF_BMLP];
            else if (i2 < OFF_WLM) {
                int j = i2 - OFF_BLM;
                v = (j < 65) ? blm[j] : 0.0f;
            } else {
                int j  = i2 - OFF_WLM;
                int c  = j / WLM_STRIDE;
                int vv = j - c * WLM_STRIDE;
                v = (vv < 65) ? Wlm[c * 65 + vv] : 0.0f;
            }
            g_pack[i2] = v;
        }
    }
}

#define KV_LS_STRIDE 264   // floats per sequence: +8 banks per ls -> conflict-free

// Main fused kernel: one thread per (sequence, token). 128 threads = 16 seqs.
// lm-head weights come from SMEM (LDS port), MLP weights from CONSTANT port.
__global__ __launch_bounds__(128, 5)
void k_main(const int* __restrict__ idx, const int* __restrict__ tgt,
            float* __restrict__ out, int write_logits,
            int loss_idx, float inv_n, int nblocks) {
    // union: K at [ls*264+s*32], V at [4224+...]; later logits stage [128][65] dense
    __shared__ __align__(16) float s_un[8448];
    __shared__ __align__(16) float s_wb[WB_N];   // [blm 68][wlm 32*68]
    __shared__ float               s_lred[4];

    const float* c_wmlp = c_all + OFF_WMLP;
    const float* c_bmlp = c_all + OFF_BMLP;
    const float* s_blm  = s_wb;
    const float* s_wlm  = s_wb + 68;

    const int tid  = threadIdx.x;
    const int ls   = tid >> 3;                 // local sequence 0..15
    const int t    = tid & 7;                  // token position
    const int rowg = blockIdx.x * 128 + tid;   // global token row
    const int tok  = idx[rowg];
    const int tgtv = tgt[rowg];
    const int qrow = (t * 65 + tok) * 32;

    // stage lm-head weights into smem (561 float4 loads across 128 threads)
    {
        const float4* src = reinterpret_cast<const float4*>(g_pack + OFF_BLM);
        float4*       dst = reinterpret_cast<float4*>(s_wb);
        for (int i = tid; i < WB_N / 4; i += 128) dst[i] = src[i];
    }

    // k, v rows into shared (own row; padded ls stride)
    {
        const float4* k4 = reinterpret_cast<const float4*>(g_Ktab + qrow);
        const float4* v4 = reinterpret_cast<const float4*>(g_Vtab + qrow);
        float4* skd = reinterpret_cast<float4*>(s_un + ls * KV_LS_STRIDE + t * 32);
        float4* svd = reinterpret_cast<float4*>(s_un + 4224 + ls * KV_LS_STRIDE + t * 32);
#pragma unroll
        for (int j = 0; j < 8; j++) { skd[j] = k4[j]; svd[j] = v4[j]; }
    }
    __syncthreads();

    // ----- attention in head-pairs (hp = heads {2hp, 2hp+1}) -----
    float ov[32];
#pragma unroll
    for (int hp = 0; hp < 2; hp++) {
        u64 q2[8];
        {
            const ulonglong2* q4 =
                reinterpret_cast<const ulonglong2*>(g_Qtab + qrow + hp * 16);
#pragma unroll
            for (int j = 0; j < 4; j++) {
                ulonglong2 a = q4[j];
                q2[2 * j] = a.x; q2[2 * j + 1] = a.y;
            }
        }
        float sc[2][8];
        const float* kb = s_un + ls * KV_LS_STRIDE + hp * 16;
#pragma unroll
        for (int s = 0; s < 8; s++) {
            const ulonglong2* kr = reinterpret_cast<const ulonglong2*>(kb + s * 32);
            ulonglong2 a = kr[0], b = kr[1], c = kr[2], d = kr[3];
            u64 e0 = 0ull, e1 = 0ull, f0 = 0ull, f1 = 0ull;
            e0 = fma2(q2[0], a.x, e0); e1 = fma2(q2[1], a.y, e1);
            e0 = fma2(q2[2], b.x, e0); e1 = fma2(q2[3], b.y, e1);
            f0 = fma2(q2[4], c.x, f0); f1 = fma2(q2[5], c.y, f1);
            f0 = fma2(q2[6], d.x, f0); f1 = fma2(q2[7], d.y, f1);
            float se = hadd2(add2(e0, e1));
            float sf = hadd2(add2(f0, f1));
            sc[0][s] = (s <= t) ? se : -1e30f;
            sc[1][s] = (s <= t) ? sf : -1e30f;
        }
        float rinv[2];
#pragma unroll
        for (int hh = 0; hh < 2; hh++) {
            float m = sc[hh][0];
#pragma unroll
            for (int s = 1; s < 8; s++) m = fmaxf(m, sc[hh][s]);
            float sum = 0.f;
#pragma unroll
            for (int s = 0; s < 8; s++) {
                float e = __expf(sc[hh][s] - m);   // masked lanes underflow to 0
                sc[hh][s] = e;
                sum += e;
            }
            rinv[hh] = __fdividef(1.0f, sum);
        }
        u64 oacc[8];
#pragma unroll
        for (int j = 0; j < 8; j++) oacc[j] = 0ull;
        const float* vb = s_un + 4224 + ls * KV_LS_STRIDE + hp * 16;
#pragma unroll
        for (int s = 0; s < 8; s++) {
            const ulonglong2* vr = reinterpret_cast<const ulonglong2*>(vb + s * 32);
            ulonglong2 a = vr[0], b = vr[1], c = vr[2], d = vr[3];
            float p0 = sc[0][s] * rinv[0];
            float p1 = sc[1][s] * rinv[1];
            u64 p02 = pack2(p0, p0), p12 = pack2(p1, p1);
            oacc[0] = fma2(p02, a.x, oacc[0]); oacc[1] = fma2(p02, a.y, oacc[1]);
            oacc[2] = fma2(p02, b.x, oacc[2]); oacc[3] = fma2(p02, b.y, oacc[3]);
            oacc[4] = fma2(p12, c.x, oacc[4]); oacc[5] = fma2(p12, c.y, oacc[5]);
            oacc[6] = fma2(p12, d.x, oacc[6]); oacc[7] = fma2(p12, d.y, oacc[7]);
        }
#pragma unroll
        for (int j = 0; j < 8; j++) {
            ov[hp * 16 + 2 * j]     = lo2(oacc[j]);
            ov[hp * 16 + 2 * j + 1] = hi2(oacc[j]);
        }
    }
    __syncthreads();   // done reading K/V -> union becomes logits stage

    // ----- MLP: y = relu(ov @ Wmlp + b); CONSTANT port -----
    u64 macc[16];
#pragma unroll
    for (int j = 0; j < 8; j++) {
        ulonglong2 b = ldc4(c_bmlp + 4 * j);
        macc[2 * j] = b.x; macc[2 * j + 1] = b.y;
    }
#pragma unroll
    for (int c = 0; c < 32; c++) {
        u64 xb = pack2(ov[c], ov[c]);
#pragma unroll
        for (int jj = 0; jj < 8; jj++) {
            ulonglong2 w = ldc4(c_wmlp + c * 32 + 4 * jj);
            macc[2 * jj]     = fma2(xb, w.x, macc[2 * jj]);
            macc[2 * jj + 1] = fma2(xb, w.y, macc[2 * jj + 1]);
        }
    }
    float y[32];
#pragma unroll
    for (int j = 0; j < 16; j++) {
        y[2 * j]     = fmaxf(lo2(macc[j]), 0.f);
        y[2 * j + 1] = fmaxf(hi2(macc[j]), 0.f);
    }

    // ----- lm-head: weights via uniform LDS.128 (LDS port); online LSE -----
    float* stagerow = s_un + tid * 65;          // dense stage = output layout
    float m = -1e30f, sum = 0.f;

#pragma unroll
    for (int chunk = 0; chunk < 4; chunk++) {      // vocab [16*chunk, 16*chunk+16)
        const int vb = chunk * 16;
        u64 acc[8];
#pragma unroll
        for (int p = 0; p < 4; p++) {
            ulonglong2 b = *reinterpret_cast<const ulonglong2*>(s_blm + vb + 4 * p);
            acc[2 * p] = b.x; acc[2 * p + 1] = b.y;
        }
#pragma unroll
        for (int c = 0; c < 32; c++) {
            u64 yb = pack2(y[c], y[c]);
            const float* wr = s_wlm + c * WLM_STRIDE + vb;
#pragma unroll
            for (int q = 0; q < 4; q++) {
                ulonglong2 w = *reinterpret_cast<const ulonglong2*>(wr + 4 * q);
                acc[2 * q]     = fma2(yb, w.x, acc[2 * q]);
                acc[2 * q + 1] = fma2(yb, w.y, acc[2 * q + 1]);
            }
        }
        // store + online LSE over these 16 logits
        float cm = -1e30f;
        float l[16];
#pragma unroll
        for (int p = 0; p < 8; p++) {
            l[2 * p] = lo2(acc[p]); l[2 * p + 1] = hi2(acc[p]);
            stagerow[vb + 2 * p]     = l[2 * p];
            stagerow[vb + 2 * p + 1] = l[2 * p + 1];
            cm = fmaxf(cm, fmaxf(l[2 * p], l[2 * p + 1]));
        }
        float mn = fmaxf(m, cm);
        float s2 = sum * __expf(m - mn);
#pragma unroll
        for (int p = 0; p < 16; p++) s2 += __expf(l[p] - mn);
        m = mn; sum = s2;
    }
    {   // epilogue: v = 64
        u64 acc = *reinterpret_cast<const u64*>(s_blm + 64);
#pragma unroll
        for (int c = 0; c < 32; c++) {
            u64 yb = pack2(y[c], y[c]);
            u64 w = *reinterpret_cast<const u64*>(s_wlm + c * WLM_STRIDE + 64);
            acc = fma2(yb, w, acc);
        }
        float l64 = lo2(acc);
        stagerow[64] = l64;
        float mn = fmaxf(m, l64);
        sum = sum * __expf(m - mn) + __expf(l64 - mn);
        m = mn;
    }
    float ltgt  = stagerow[tgtv];              // own row, no sync needed
    float lossi = (m + __logf(sum)) - ltgt;

    // warp then block reduce, one atomic per block; last block writes mean
#pragma unroll
    for (int off = 16; off > 0; off >>= 1)
        lossi += __shfl_down_sync(0xffffffffu, lossi, off);
    if ((tid & 31) == 0) s_lred[tid >> 5] = lossi;
    __syncthreads();    // also guarantees stage[] fully written for the bulk store
    if (tid == 0) {
        atomicAdd(&g_loss, s_lred[0] + s_lred[1] + s_lred[2] + s_lred[3]);
        __threadfence();
        unsigned prev = atomicAdd(&g_done, 1u);
        if ((int)prev == nblocks - 1 && loss_idx >= 0)
            out[loss_idx] = g_loss * inv_n;
    }

    // ----- single TMA bulk store: SMEM stage -> GMEM logits (33280 B) -----
    if (write_logits && tid == 0) {
        unsigned int saddr;
        asm("{ .reg .u64 tmp; cvta.to.shared.u64 tmp, %1; cvt.u32.u64 %0, tmp; }"
            : "=r"(saddr) : "l"(s_un));
        const float* gdst = out + (size_t)blockIdx.x * 8320;
        asm volatile("fence.proxy.async.shared::cta;" ::: "memory");
        asm volatile("cp.async.bulk.global.shared::cta.bulk_group [%0], [%1], %2;"
                     :: "l"(gdst), "r"(saddr), "r"(33280) : "memory");
        asm volatile("cp.async.bulk.commit_group;" ::: "memory");
        asm volatile("cp.async.bulk.wait_group.read 0;" ::: "memory");
    }
}

extern "C" void kernel_launch(void* const* d_in, const int* in_sizes, int n_in,
                              void* d_out, int out_size) {
    const int*   idx     = (const int*)d_in[0];
    const int*   targets = (const int*)d_in[1];
    const float* tok_emb = (const float*)d_in[2];
    const float* pos_emb = (const float*)d_in[3];
    const float* Wq      = (const float*)d_in[4];
    const float* Wk      = (const float*)d_in[5];
    const float* Wv      = (const float*)d_in[6];
    const float* Wmlp    = (const float*)d_in[7];
    const float* bmlp    = (const float*)d_in[8];
    const float* Wlm     = (const float*)d_in[9];
    const float* blm     = (const float*)d_in[10];
    float* out = (float*)d_out;

    const long nrows = in_sizes[0];           // B*T = 524288
    const long total = nrows * VOCAB;         // logits element count
    int write_logits = ((long)out_size >= total) ? 1 : 0;
    int loss_idx = -1;
    if ((long)out_size == total + 1) loss_idx = (int)total;
    else if (out_size == 1)          { loss_idx = 0; write_logits = 0; }

    // Tables + weight packing, then ONE constant upload (D2D, capturable)
    int work = 520 * 32 + PACK_N;
    k_tables<<<(work + 255) / 256, 256>>>(tok_emb, pos_emb, Wq, Wk, Wv,
                                          Wmlp, bmlp, Wlm, blm);
    {
        void* src = nullptr;
        cudaGetSymbolAddress(&src, g_pack);
        cudaMemcpyToSymbolAsync(c_all, src, PACK_N * sizeof(float), 0,
                                cudaMemcpyDeviceToDevice);
    }

    int nblocks = (int)(nrows / 128);
    k_main<<<nblocks, 128>>>(idx, targets, out, write_logits, loss_idx,
                             1.0f / (float)nrows, nblocks);
}